// round 5
// baseline (speedup 1.0000x reference)
#include <cuda_runtime.h>

#define Bz   2
#define Tz   2048
#define DIMz 1024
#define Hz   16
#define HDz  64
#define Mz   (Bz*Tz)      /* 4096 */
#define N3z  (3*DIMz)     /* 3072 */

typedef unsigned long long ULL;

// ---------------- scratch (device globals: allocation-free) ----------------
__device__ float g_q  [Bz*Hz*Tz*HDz];   // [b][h][t][d]
__device__ float g_kT [Bz*Hz*HDz*Tz];   // [b][h][d][t]  (transposed for attention)
__device__ float g_v  [Bz*Hz*Tz*HDz];   // [b][h][t][d]
__device__ float g_att[Mz*DIMz];        // [b*t][dim]
__device__ float g_cos[Tz*HDz];
__device__ float g_sin[Tz*HDz];

// ---------------- f32x2 packed helpers ----------------
__device__ __forceinline__ ULL pack2(float x) {
    ULL r; unsigned u = __float_as_uint(x);
    asm("mov.b64 %0, {%1, %1};" : "=l"(r) : "r"(u));
    return r;
}
__device__ __forceinline__ void fma2(ULL &d, ULL a, ULL b) {
    asm("fma.rn.f32x2 %0, %1, %2, %0;" : "+l"(d) : "l"(a), "l"(b));
}
__device__ __forceinline__ void mul2(ULL &d, ULL a) {
    asm("mul.rn.f32x2 %0, %0, %1;" : "+l"(d) : "l"(a));
}
__device__ __forceinline__ float2 unpack2(ULL v) {
    float2 r;
    r.x = __uint_as_float((unsigned)v);
    r.y = __uint_as_float((unsigned)(v >> 32));
    return r;
}

#define GETC(f4, dd) ((dd)==0 ? (f4).x : (dd)==1 ? (f4).y : (dd)==2 ? (f4).z : (f4).w)

// ---------------- RoPE cos/sin tables ----------------
__global__ void rope_tables_kernel() {
    int idx = blockIdx.x * 256 + threadIdx.x;      // < Tz*HDz
    int t = idx >> 6, d = idx & 63;
    // inv_freq = 10000^(-(d%32)/32)
    float inv = expf(-(float)(d & 31) * (9.210340371976184f / 32.0f));
    float ang = (float)t * inv;
    g_cos[idx] = cosf(ang);
    g_sin[idx] = sinf(ang);
}

// ---------------- QKV GEMM (M=4096, N=3072, K=1024) + RoPE epilogue ----------------
// 128x128 tile, 256 threads, 8x8 microtile (cols split as [tx*4 .. +3] and [64+tx*4 .. +3])
__global__ __launch_bounds__(256, 2)
void qkv_rope_kernel(const float* __restrict__ x, const float* __restrict__ W) {
    __shared__ __align__(16) float As[128 * 16];   // [row][kk]
    __shared__ __align__(16) float Bs[16 * 128];   // [kk][col]
    const int tid = threadIdx.x;
    const int ty = tid >> 4, tx = tid & 15;
    const int m0 = blockIdx.y * 128;
    const int n0 = blockIdx.x * 128;

    ULL acc[8][4];
#pragma unroll
    for (int i = 0; i < 8; ++i)
#pragma unroll
        for (int j = 0; j < 4; ++j) acc[i][j] = 0ULL;

    for (int kt = 0; kt < 64; ++kt) {
        const int k0 = kt * 16;
#pragma unroll
        for (int s = 0; s < 2; ++s) {
            int e = tid + s * 256;
            int row = e >> 2, kseg = e & 3;
            *(float4*)&As[row * 16 + kseg * 4] =
                *(const float4*)&x[(m0 + row) * 1024 + k0 + kseg * 4];
            int kk = e >> 5, nseg = e & 31;
            *(float4*)&Bs[kk * 128 + nseg * 4] =
                *(const float4*)&W[(k0 + kk) * 3072 + n0 + nseg * 4];
        }
        __syncthreads();
#pragma unroll
        for (int kk = 0; kk < 16; ++kk) {
            const float* br = &Bs[kk * 128];
            ULL b0 = *(const ULL*)(br + tx * 4);
            ULL b1 = *(const ULL*)(br + tx * 4 + 2);
            ULL b2 = *(const ULL*)(br + 64 + tx * 4);
            ULL b3 = *(const ULL*)(br + 64 + tx * 4 + 2);
#pragma unroll
            for (int i = 0; i < 8; ++i) {
                ULL ap = pack2(As[(ty * 8 + i) * 16 + kk]);
                fma2(acc[i][0], ap, b0);
                fma2(acc[i][1], ap, b1);
                fma2(acc[i][2], ap, b2);
                fma2(acc[i][3], ap, b3);
            }
        }
        __syncthreads();
    }

    // epilogue: which 0=q,1=k,2=v; each 64-wide col group is exactly one head
    const int which = n0 >> 10;
    const int bb    = m0 >> 11;
    const int hbase = (n0 & 1023) >> 6;     // even; groups are hbase and hbase+1
    const int d0    = tx * 4;               // in-head dim offset (same for both groups)

#pragma unroll
    for (int i = 0; i < 8; ++i) {
        const int t = (m0 & 2047) + ty * 8 + i;
        float2 p0 = unpack2(acc[i][0]), p1 = unpack2(acc[i][1]);
        float2 p2 = unpack2(acc[i][2]), p3 = unpack2(acc[i][3]);
        float c0[4] = {p0.x, p0.y, p1.x, p1.y};
        float c1[4] = {p2.x, p2.y, p3.x, p3.y};

        if (which == 2) {
            *(float4*)&g_v[(((size_t)(bb * Hz + hbase)     * Tz + t) * HDz) + d0] =
                make_float4(c0[0], c0[1], c0[2], c0[3]);
            *(float4*)&g_v[(((size_t)(bb * Hz + hbase + 1) * Tz + t) * HDz) + d0] =
                make_float4(c1[0], c1[1], c1[2], c1[3]);
        } else {
            float4 cs = *(const float4*)&g_cos[t * 64 + d0];
            float4 sn = *(const float4*)&g_sin[t * 64 + d0];
            float r0[4], r1[4];
            // pairs (even,odd): out_e = v_e*cos_e - v_o*sin_e ; out_o = v_o*cos_o + v_e*sin_o
            r0[0] = c0[0] * cs.x - c0[1] * sn.x;  r0[1] = c0[1] * cs.y + c0[0] * sn.y;
            r0[2] = c0[2] * cs.z - c0[3] * sn.z;  r0[3] = c0[3] * cs.w + c0[2] * sn.w;
            r1[0] = c1[0] * cs.x - c1[1] * sn.x;  r1[1] = c1[1] * cs.y + c1[0] * sn.y;
            r1[2] = c1[2] * cs.z - c1[3] * sn.z;  r1[3] = c1[3] * cs.w + c1[2] * sn.w;

            if (which == 0) {
                *(float4*)&g_q[(((size_t)(bb * Hz + hbase)     * Tz + t) * HDz) + d0] =
                    make_float4(r0[0], r0[1], r0[2], r0[3]);
                *(float4*)&g_q[(((size_t)(bb * Hz + hbase + 1) * Tz + t) * HDz) + d0] =
                    make_float4(r1[0], r1[1], r1[2], r1[3]);
            } else {
                size_t base0 = ((size_t)(bb * Hz + hbase)     * HDz + d0) * Tz + t;
                size_t base1 = ((size_t)(bb * Hz + hbase + 1) * HDz + d0) * Tz + t;
#pragma unroll
                for (int j = 0; j < 4; ++j) {
                    g_kT[base0 + (size_t)j * Tz] = r0[j];
                    g_kT[base1 + (size_t)j * Tz] = r1[j];
                }
            }
        }
    }
}

// ---------------- Flash attention: 1 block per (b, h, 64-query tile) ----------------
__global__ __launch_bounds__(256)
void attn_kernel() {
    extern __shared__ __align__(16) float sm[];
    float* Qs = sm;                 // [64 q][64 d]   (pre-scaled by 1/8)
    float* Ks = sm + 64 * 64;       // [64 d][64 k]
    float* Vs = sm + 2 * 64 * 64;   // [64 k][64 d]
    float* Ps = sm + 3 * 64 * 64;   // [64 q][64 k]

    const int tid = threadIdx.x;
    const int ty = tid >> 4, tx = tid & 15;
    const int qt = blockIdx.x, h = blockIdx.y, bb = blockIdx.z;

    const float* Qg = g_q  + ((size_t)(bb * Hz + h) * Tz + qt * 64) * HDz;
    const float* Kg = g_kT + (size_t)(bb * Hz + h) * HDz * Tz;
    const float* Vg = g_v  + (size_t)(bb * Hz + h) * Tz * HDz;

#pragma unroll
    for (int s = 0; s < 4; ++s) {
        int e = tid + s * 256;
        int r = e >> 4, dseg = e & 15;
        float4 v = *(const float4*)&Qg[r * HDz + dseg * 4];
        v.x *= 0.125f; v.y *= 0.125f; v.z *= 0.125f; v.w *= 0.125f;
        *(float4*)&Qs[r * 64 + dseg * 4] = v;
    }

    ULL o2[4][2];
    float mi[4], li[4];
#pragma unroll
    for (int i = 0; i < 4; ++i) { o2[i][0] = 0; o2[i][1] = 0; mi[i] = -1e30f; li[i] = 0.f; }
    __syncthreads();

    for (int kt = 0; kt < 32; ++kt) {
#pragma unroll
        for (int s = 0; s < 4; ++s) {
            int e = tid + s * 256;
            int a = e >> 4, seg = e & 15;
            *(float4*)&Ks[a * 64 + seg * 4] = *(const float4*)&Kg[(size_t)a * Tz + kt * 64 + seg * 4];
            *(float4*)&Vs[a * 64 + seg * 4] = *(const float4*)&Vg[(kt * 64 + a) * HDz + seg * 4];
        }
        __syncthreads();

        // GEMM1: S = Qs @ Ks  (already scaled)
        ULL s2[4][2];
#pragma unroll
        for (int i = 0; i < 4; ++i) { s2[i][0] = 0; s2[i][1] = 0; }
#pragma unroll 4
        for (int d4 = 0; d4 < 16; ++d4) {
            float4 q0 = *(const float4*)&Qs[(ty * 4 + 0) * 64 + d4 * 4];
            float4 q1 = *(const float4*)&Qs[(ty * 4 + 1) * 64 + d4 * 4];
            float4 q2 = *(const float4*)&Qs[(ty * 4 + 2) * 64 + d4 * 4];
            float4 q3 = *(const float4*)&Qs[(ty * 4 + 3) * 64 + d4 * 4];
#pragma unroll
            for (int dd = 0; dd < 4; ++dd) {
                const float* kr = &Ks[(d4 * 4 + dd) * 64 + tx * 4];
                ULL k0 = *(const ULL*)kr;
                ULL k1 = *(const ULL*)(kr + 2);
                ULL a0 = pack2(GETC(q0, dd)); fma2(s2[0][0], a0, k0); fma2(s2[0][1], a0, k1);
                ULL a1 = pack2(GETC(q1, dd)); fma2(s2[1][0], a1, k0); fma2(s2[1][1], a1, k1);
                ULL a2 = pack2(GETC(q2, dd)); fma2(s2[2][0], a2, k0); fma2(s2[2][1], a2, k1);
                ULL a3 = pack2(GETC(q3, dd)); fma2(s2[3][0], a3, k0); fma2(s2[3][1], a3, k1);
            }
        }

        // online softmax (row groups live in 16-lane half-warps)
#pragma unroll
        for (int i = 0; i < 4; ++i) {
            float2 sa = unpack2(s2[i][0]), sb = unpack2(s2[i][1]);
            float v0 = sa.x, v1 = sa.y, v2 = sb.x, v3 = sb.y;
            float mx = fmaxf(fmaxf(v0, v1), fmaxf(v2, v3));
            mx = fmaxf(mx, __shfl_xor_sync(0xffffffffu, mx, 1));
            mx = fmaxf(mx, __shfl_xor_sync(0xffffffffu, mx, 2));
            mx = fmaxf(mx, __shfl_xor_sync(0xffffffffu, mx, 4));
            mx = fmaxf(mx, __shfl_xor_sync(0xffffffffu, mx, 8));
            float mnew = fmaxf(mi[i], mx);
            float f = __expf(mi[i] - mnew);
            mi[i] = mnew;
            float p0 = __expf(v0 - mnew), p1 = __expf(v1 - mnew);
            float p2 = __expf(v2 - mnew), p3 = __expf(v3 - mnew);
            float ls = p0 + p1 + p2 + p3;
            ls += __shfl_xor_sync(0xffffffffu, ls, 1);
            ls += __shfl_xor_sync(0xffffffffu, ls, 2);
            ls += __shfl_xor_sync(0xffffffffu, ls, 4);
            ls += __shfl_xor_sync(0xffffffffu, ls, 8);
            li[i] = li[i] * f + ls;
            ULL f2 = pack2(f);
            mul2(o2[i][0], f2);
            mul2(o2[i][1], f2);
            *(float4*)&Ps[(ty * 4 + i) * 64 + tx * 4] = make_float4(p0, p1, p2, p3);
        }
        __syncthreads();

        // GEMM2: O += P @ V
#pragma unroll 4
        for (int k4 = 0; k4 < 16; ++k4) {
            float4 P0 = *(const float4*)&Ps[(ty * 4 + 0) * 64 + k4 * 4];
            float4 P1 = *(const float4*)&Ps[(ty * 4 + 1) * 64 + k4 * 4];
            float4 P2 = *(const float4*)&Ps[(ty * 4 + 2) * 64 + k4 * 4];
            float4 P3 = *(const float4*)&Ps[(ty * 4 + 3) * 64 + k4 * 4];
#pragma unroll
            for (int dd = 0; dd < 4; ++dd) {
                const float* vr = &Vs[(k4 * 4 + dd) * 64 + tx * 4];
                ULL w0 = *(const ULL*)vr;
                ULL w1 = *(const ULL*)(vr + 2);
                ULL a0 = pack2(GETC(P0, dd)); fma2(o2[0][0], a0, w0); fma2(o2[0][1], a0, w1);
                ULL a1 = pack2(GETC(P1, dd)); fma2(o2[1][0], a1, w0); fma2(o2[1][1], a1, w1);
                ULL a2 = pack2(GETC(P2, dd)); fma2(o2[2][0], a2, w0); fma2(o2[2][1], a2, w1);
                ULL a3 = pack2(GETC(P3, dd)); fma2(o2[3][0], a3, w0); fma2(o2[3][1], a3, w1);
            }
        }
        __syncthreads();
    }

    // epilogue: normalize and write [b][t][h*64+d]
#pragma unroll
    for (int i = 0; i < 4; ++i) {
        float inv = 1.0f / li[i];
        float2 a = unpack2(o2[i][0]);
        float2 c = unpack2(o2[i][1]);
        int t = qt * 64 + ty * 4 + i;
        *(float4*)&g_att[((size_t)(bb * Tz + t)) * DIMz + h * 64 + tx * 4] =
            make_float4(a.x * inv, a.y * inv, c.x * inv, c.y * inv);
    }
}

// ---------------- Output projection (M=4096, N=1024, K=1024) + bias ----------------
__global__ __launch_bounds__(256, 2)
void proj_kernel(const float* __restrict__ W, const float* __restrict__ bias,
                 float* __restrict__ out) {
    __shared__ __align__(16) float As[128 * 16];
    __shared__ __align__(16) float Bs[16 * 128];
    const int tid = threadIdx.x;
    const int ty = tid >> 4, tx = tid & 15;
    const int m0 = blockIdx.y * 128;
    const int n0 = blockIdx.x * 128;

    ULL acc[8][4];
#pragma unroll
    for (int i = 0; i < 8; ++i)
#pragma unroll
        for (int j = 0; j < 4; ++j) acc[i][j] = 0ULL;

    for (int kt = 0; kt < 64; ++kt) {
        const int k0 = kt * 16;
#pragma unroll
        for (int s = 0; s < 2; ++s) {
            int e = tid + s * 256;
            int row = e >> 2, kseg = e & 3;
            *(float4*)&As[row * 16 + kseg * 4] =
                *(const float4*)&g_att[(size_t)(m0 + row) * 1024 + k0 + kseg * 4];
            int kk = e >> 5, nseg = e & 31;
            *(float4*)&Bs[kk * 128 + nseg * 4] =
                *(const float4*)&W[(k0 + kk) * 1024 + n0 + nseg * 4];
        }
        __syncthreads();
#pragma unroll
        for (int kk = 0; kk < 16; ++kk) {
            const float* br = &Bs[kk * 128];
            ULL b0 = *(const ULL*)(br + tx * 4);
            ULL b1 = *(const ULL*)(br + tx * 4 + 2);
            ULL b2 = *(const ULL*)(br + 64 + tx * 4);
            ULL b3 = *(const ULL*)(br + 64 + tx * 4 + 2);
#pragma unroll
            for (int i = 0; i < 8; ++i) {
                ULL ap = pack2(As[(ty * 8 + i) * 16 + kk]);
                fma2(acc[i][0], ap, b0);
                fma2(acc[i][1], ap, b1);
                fma2(acc[i][2], ap, b2);
                fma2(acc[i][3], ap, b3);
            }
        }
        __syncthreads();
    }

    float4 bi0 = *(const float4*)&bias[n0 + tx * 4];
    float4 bi1 = *(const float4*)&bias[n0 + 64 + tx * 4];
#pragma unroll
    for (int i = 0; i < 8; ++i) {
        int m = m0 + ty * 8 + i;
        float2 p0 = unpack2(acc[i][0]), p1 = unpack2(acc[i][1]);
        float2 p2 = unpack2(acc[i][2]), p3 = unpack2(acc[i][3]);
        *(float4*)&out[(size_t)m * 1024 + n0 + tx * 4] =
            make_float4(p0.x + bi0.x, p0.y + bi0.y, p1.x + bi0.z, p1.y + bi0.w);
        *(float4*)&out[(size_t)m * 1024 + n0 + 64 + tx * 4] =
            make_float4(p2.x + bi1.x, p2.y + bi1.y, p3.x + bi1.z, p3.y + bi1.w);
    }
}

// ---------------- launch ----------------
extern "C" void kernel_launch(void* const* d_in, const int* in_sizes, int n_in,
                              void* d_out, int out_size) {
    (void)in_sizes; (void)n_in; (void)out_size;
    const float* x    = (const float*)d_in[0];
    const float* Wqkv = (const float*)d_in[1];
    const float* Wout = (const float*)d_in[2];
    const float* bout = (const float*)d_in[3];
    float* out = (float*)d_out;

    cudaFuncSetAttribute(attn_kernel, cudaFuncAttributeMaxDynamicSharedMemorySize, 65536);

    rope_tables_kernel<<<(Tz * HDz) / 256, 256>>>();
    qkv_rope_kernel<<<dim3(N3z / 128, Mz / 128), 256>>>(x, Wqkv);
    attn_kernel<<<dim3(Tz / 64, Hz, Bz), 256, 65536>>>();
    proj_kernel<<<dim3(DIMz / 128, Mz / 128), 256>>>(Wout, bout, out);
}

// round 6
// speedup vs baseline: 1.0658x; 1.0658x over previous
#include <cuda_runtime.h>

#define Bz   2
#define Tz   2048
#define DIMz 1024
#define Hz   16
#define HDz  64
#define Mz   (Bz*Tz)      /* 4096 */
#define N3z  (3*DIMz)     /* 3072 */

typedef unsigned long long ULL;

// ---------------- scratch (device globals: allocation-free) ----------------
__device__ float g_q  [Bz*Hz*Tz*HDz];   // [b][h][t][d]
__device__ float g_kT [Bz*Hz*HDz*Tz];   // [b][h][d][t]  (transposed for attention)
__device__ float g_v  [Bz*Hz*Tz*HDz];   // [b][h][t][d]
__device__ float g_att[Mz*DIMz];        // [b*t][dim]
__device__ float g_cos[Tz*HDz];
__device__ float g_sin[Tz*HDz];

// ---------------- f32x2 packed helpers ----------------
__device__ __forceinline__ ULL pack2(float x) {
    ULL r; unsigned u = __float_as_uint(x);
    asm("mov.b64 %0, {%1, %1};" : "=l"(r) : "r"(u));
    return r;
}
__device__ __forceinline__ void fma2(ULL &d, ULL a, ULL b) {
    asm("fma.rn.f32x2 %0, %1, %2, %0;" : "+l"(d) : "l"(a), "l"(b));
}
__device__ __forceinline__ void mul2(ULL &d, ULL a) {
    asm("mul.rn.f32x2 %0, %0, %1;" : "+l"(d) : "l"(a));
}
__device__ __forceinline__ float2 unpack2(ULL v) {
    float2 r;
    r.x = __uint_as_float((unsigned)v);
    r.y = __uint_as_float((unsigned)(v >> 32));
    return r;
}

#define GETC(f4, dd) ((dd)==0 ? (f4).x : (dd)==1 ? (f4).y : (dd)==2 ? (f4).z : (f4).w)

// ---------------- cp.async helpers ----------------
__device__ __forceinline__ void cp16(float* dst, const float* src) {
    unsigned d = (unsigned)__cvta_generic_to_shared(dst);
    asm volatile("cp.async.cg.shared.global [%0], [%1], 16;" :: "r"(d), "l"(src));
}
#define CP_COMMIT() asm volatile("cp.async.commit_group;")
#define CP_WAIT0()  asm volatile("cp.async.wait_group 0;")

// ---------------- RoPE cos/sin tables ----------------
__global__ void rope_tables_kernel() {
    int idx = blockIdx.x * 256 + threadIdx.x;      // < Tz*HDz
    int t = idx >> 6, d = idx & 63;
    float inv = expf(-(float)(d & 31) * (9.210340371976184f / 32.0f));
    float ang = (float)t * inv;
    g_cos[idx] = cosf(ang);
    g_sin[idx] = sinf(ang);
}

// ---------------- QKV GEMM (M=4096, N=3072, K=1024) + RoPE epilogue ----------------
// 128x128 tile, 256 threads, 8x8 microtile, double-buffered cp.async pipeline.
__global__ __launch_bounds__(256, 2)
void qkv_rope_kernel(const float* __restrict__ x, const float* __restrict__ W) {
    __shared__ __align__(16) float As[2][128 * 16];   // [row][kk]
    __shared__ __align__(16) float Bs[2][16 * 128];   // [kk][col]
    const int tid = threadIdx.x;
    const int ty = tid >> 4, tx = tid & 15;
    const int m0 = blockIdx.y * 128;
    const int n0 = blockIdx.x * 128;

    const int rA0 = tid >> 2,          ksA0 = tid & 3;
    const int rA1 = (tid + 256) >> 2,  ksA1 = (tid + 256) & 3;
    const int kB0 = tid >> 5,          nsB0 = tid & 31;
    const int kB1 = (tid + 256) >> 5,  nsB1 = (tid + 256) & 31;

    ULL acc[8][4];
#pragma unroll
    for (int i = 0; i < 8; ++i)
#pragma unroll
        for (int j = 0; j < 4; ++j) acc[i][j] = 0ULL;

    // prologue: stage tile 0
    {
        cp16(&As[0][rA0 * 16 + ksA0 * 4], &x[(size_t)(m0 + rA0) * 1024 + ksA0 * 4]);
        cp16(&As[0][rA1 * 16 + ksA1 * 4], &x[(size_t)(m0 + rA1) * 1024 + ksA1 * 4]);
        cp16(&Bs[0][kB0 * 128 + nsB0 * 4], &W[(size_t)kB0 * 3072 + n0 + nsB0 * 4]);
        cp16(&Bs[0][kB1 * 128 + nsB1 * 4], &W[(size_t)kB1 * 3072 + n0 + nsB1 * 4]);
        CP_COMMIT(); CP_WAIT0();
    }
    __syncthreads();

    for (int kt = 0; kt < 64; ++kt) {
        const int cur = kt & 1;
        if (kt < 63) {
            const int nxt = cur ^ 1;
            const int k0 = (kt + 1) * 16;
            cp16(&As[nxt][rA0 * 16 + ksA0 * 4], &x[(size_t)(m0 + rA0) * 1024 + k0 + ksA0 * 4]);
            cp16(&As[nxt][rA1 * 16 + ksA1 * 4], &x[(size_t)(m0 + rA1) * 1024 + k0 + ksA1 * 4]);
            cp16(&Bs[nxt][kB0 * 128 + nsB0 * 4], &W[(size_t)(k0 + kB0) * 3072 + n0 + nsB0 * 4]);
            cp16(&Bs[nxt][kB1 * 128 + nsB1 * 4], &W[(size_t)(k0 + kB1) * 3072 + n0 + nsB1 * 4]);
            CP_COMMIT();
        }
#pragma unroll
        for (int k4 = 0; k4 < 4; ++k4) {
            float4 a4[8];
#pragma unroll
            for (int i = 0; i < 8; ++i)
                a4[i] = *(const float4*)&As[cur][(ty * 8 + i) * 16 + k4 * 4];
#pragma unroll
            for (int dd = 0; dd < 4; ++dd) {
                const float* br = &Bs[cur][(k4 * 4 + dd) * 128];
                ulonglong2 u0 = *(const ulonglong2*)(br + tx * 4);
                ulonglong2 u1 = *(const ulonglong2*)(br + 64 + tx * 4);
#pragma unroll
                for (int i = 0; i < 8; ++i) {
                    ULL ap = pack2(GETC(a4[i], dd));
                    fma2(acc[i][0], ap, u0.x);
                    fma2(acc[i][1], ap, u0.y);
                    fma2(acc[i][2], ap, u1.x);
                    fma2(acc[i][3], ap, u1.y);
                }
            }
        }
        CP_WAIT0();
        __syncthreads();
    }

    // epilogue: which 0=q,1=k,2=v; each 64-wide col group is exactly one head
    const int which = n0 >> 10;
    const int bb    = m0 >> 11;
    const int hbase = (n0 & 1023) >> 6;
    const int d0    = tx * 4;

#pragma unroll
    for (int i = 0; i < 8; ++i) {
        const int t = (m0 & 2047) + ty * 8 + i;
        float2 p0 = unpack2(acc[i][0]), p1 = unpack2(acc[i][1]);
        float2 p2 = unpack2(acc[i][2]), p3 = unpack2(acc[i][3]);
        float c0[4] = {p0.x, p0.y, p1.x, p1.y};
        float c1[4] = {p2.x, p2.y, p3.x, p3.y};

        if (which == 2) {
            *(float4*)&g_v[(((size_t)(bb * Hz + hbase)     * Tz + t) * HDz) + d0] =
                make_float4(c0[0], c0[1], c0[2], c0[3]);
            *(float4*)&g_v[(((size_t)(bb * Hz + hbase + 1) * Tz + t) * HDz) + d0] =
                make_float4(c1[0], c1[1], c1[2], c1[3]);
        } else {
            float4 cs = *(const float4*)&g_cos[t * 64 + d0];
            float4 sn = *(const float4*)&g_sin[t * 64 + d0];
            float r0[4], r1[4];
            r0[0] = c0[0] * cs.x - c0[1] * sn.x;  r0[1] = c0[1] * cs.y + c0[0] * sn.y;
            r0[2] = c0[2] * cs.z - c0[3] * sn.z;  r0[3] = c0[3] * cs.w + c0[2] * sn.w;
            r1[0] = c1[0] * cs.x - c1[1] * sn.x;  r1[1] = c1[1] * cs.y + c1[0] * sn.y;
            r1[2] = c1[2] * cs.z - c1[3] * sn.z;  r1[3] = c1[3] * cs.w + c1[2] * sn.w;

            if (which == 0) {
                *(float4*)&g_q[(((size_t)(bb * Hz + hbase)     * Tz + t) * HDz) + d0] =
                    make_float4(r0[0], r0[1], r0[2], r0[3]);
                *(float4*)&g_q[(((size_t)(bb * Hz + hbase + 1) * Tz + t) * HDz) + d0] =
                    make_float4(r1[0], r1[1], r1[2], r1[3]);
            } else {
                size_t base0 = ((size_t)(bb * Hz + hbase)     * HDz + d0) * Tz + t;
                size_t base1 = ((size_t)(bb * Hz + hbase + 1) * HDz + d0) * Tz + t;
#pragma unroll
                for (int j = 0; j < 4; ++j) {
                    g_kT[base0 + (size_t)j * Tz] = r0[j];
                    g_kT[base1 + (size_t)j * Tz] = r1[j];
                }
            }
        }
    }
}

// ---------------- Flash attention: Tq=64 x Tk=128 tiles ----------------
// 256 threads, per-thread 4 q-rows x 8 k-cols (split groups tx*4 and 64+tx*4).
#define SM_QS 0
#define SM_KS 4096
#define SM_VS (4096 + 8192)
#define SM_PS (4096 + 16384)
#define SM_FLOATS (4096 + 8192 + 8192 + 8192)

__global__ __launch_bounds__(256, 2)
void attn_kernel() {
    extern __shared__ __align__(16) float sm[];
    float* Qs = sm + SM_QS;   // [64 q][64 d]  (pre-scaled by 1/8)
    float* Ks = sm + SM_KS;   // [64 d][128 k]
    float* Vs = sm + SM_VS;   // [128 k][64 d]
    float* Ps = sm + SM_PS;   // [64 q][128 k]

    const int tid = threadIdx.x;
    const int ty = tid >> 4, tx = tid & 15;
    const int qt = blockIdx.x, h = blockIdx.y, bb = blockIdx.z;

    const float* Qg = g_q  + ((size_t)(bb * Hz + h) * Tz + qt * 64) * HDz;
    const float* Kg = g_kT + (size_t)(bb * Hz + h) * HDz * Tz;
    const float* Vg = g_v  + (size_t)(bb * Hz + h) * Tz * HDz;

#pragma unroll
    for (int s = 0; s < 4; ++s) {
        int e = tid + s * 256;
        int r = e >> 4, seg = e & 15;
        float4 v = *(const float4*)&Qg[r * HDz + seg * 4];
        v.x *= 0.125f; v.y *= 0.125f; v.z *= 0.125f; v.w *= 0.125f;
        *(float4*)&Qs[r * 64 + seg * 4] = v;
    }

    ULL o2[4][2];
    float mi[4], li[4];
#pragma unroll
    for (int i = 0; i < 4; ++i) { o2[i][0] = 0; o2[i][1] = 0; mi[i] = -1e30f; li[i] = 0.f; }
    __syncthreads();

    for (int kt = 0; kt < 16; ++kt) {
        // stage K (transposed layout [d][k]) and V ([k][d])
#pragma unroll
        for (int s = 0; s < 8; ++s) {
            int e = tid + s * 256;
            int d = e >> 5, seg = e & 31;
            *(float4*)&Ks[d * 128 + seg * 4] =
                *(const float4*)&Kg[(size_t)d * Tz + kt * 128 + seg * 4];
        }
#pragma unroll
        for (int s = 0; s < 8; ++s) {
            int e = tid + s * 256;
            int k = e >> 4, seg = e & 15;
            *(float4*)&Vs[k * 64 + seg * 4] =
                *(const float4*)&Vg[(size_t)(kt * 128 + k) * HDz + seg * 4];
        }
        __syncthreads();

        // GEMM1: S = Qs @ Ks   (Q pre-scaled)
        ULL s2[4][4];
#pragma unroll
        for (int i = 0; i < 4; ++i)
#pragma unroll
            for (int j = 0; j < 4; ++j) s2[i][j] = 0ULL;

#pragma unroll 4
        for (int d4 = 0; d4 < 16; ++d4) {
            float4 q[4];
#pragma unroll
            for (int i = 0; i < 4; ++i)
                q[i] = *(const float4*)&Qs[(ty * 4 + i) * 64 + d4 * 4];
#pragma unroll
            for (int dd = 0; dd < 4; ++dd) {
                const float* kr = &Ks[(d4 * 4 + dd) * 128];
                ulonglong2 ka = *(const ulonglong2*)(kr + tx * 4);
                ulonglong2 kb = *(const ulonglong2*)(kr + 64 + tx * 4);
#pragma unroll
                for (int i = 0; i < 4; ++i) {
                    ULL ap = pack2(GETC(q[i], dd));
                    fma2(s2[i][0], ap, ka.x);
                    fma2(s2[i][1], ap, ka.y);
                    fma2(s2[i][2], ap, kb.x);
                    fma2(s2[i][3], ap, kb.y);
                }
            }
        }

        // online softmax (rows live in 16-lane half-warps)
#pragma unroll
        for (int i = 0; i < 4; ++i) {
            float2 sa = unpack2(s2[i][0]), sb = unpack2(s2[i][1]);
            float2 sc = unpack2(s2[i][2]), sd = unpack2(s2[i][3]);
            float v0 = sa.x, v1 = sa.y, v2 = sb.x, v3 = sb.y;
            float v4 = sc.x, v5 = sc.y, v6 = sd.x, v7 = sd.y;
            float mx = fmaxf(fmaxf(fmaxf(v0, v1), fmaxf(v2, v3)),
                             fmaxf(fmaxf(v4, v5), fmaxf(v6, v7)));
            mx = fmaxf(mx, __shfl_xor_sync(0xffffffffu, mx, 1));
            mx = fmaxf(mx, __shfl_xor_sync(0xffffffffu, mx, 2));
            mx = fmaxf(mx, __shfl_xor_sync(0xffffffffu, mx, 4));
            mx = fmaxf(mx, __shfl_xor_sync(0xffffffffu, mx, 8));
            float mnew = fmaxf(mi[i], mx);
            float f = __expf(mi[i] - mnew);
            mi[i] = mnew;
            float p0 = __expf(v0 - mnew), p1 = __expf(v1 - mnew);
            float p2 = __expf(v2 - mnew), p3 = __expf(v3 - mnew);
            float p4 = __expf(v4 - mnew), p5 = __expf(v5 - mnew);
            float p6 = __expf(v6 - mnew), p7 = __expf(v7 - mnew);
            float ls = (p0 + p1) + (p2 + p3) + (p4 + p5) + (p6 + p7);
            ls += __shfl_xor_sync(0xffffffffu, ls, 1);
            ls += __shfl_xor_sync(0xffffffffu, ls, 2);
            ls += __shfl_xor_sync(0xffffffffu, ls, 4);
            ls += __shfl_xor_sync(0xffffffffu, ls, 8);
            li[i] = li[i] * f + ls;
            ULL f2 = pack2(f);
            mul2(o2[i][0], f2);
            mul2(o2[i][1], f2);
            *(float4*)&Ps[(ty * 4 + i) * 128 + tx * 4]      = make_float4(p0, p1, p2, p3);
            *(float4*)&Ps[(ty * 4 + i) * 128 + 64 + tx * 4] = make_float4(p4, p5, p6, p7);
        }
        __syncthreads();

        // GEMM2: O += P @ V
#pragma unroll 4
        for (int k4 = 0; k4 < 32; ++k4) {
            float4 p[4];
#pragma unroll
            for (int i = 0; i < 4; ++i)
                p[i] = *(const float4*)&Ps[(ty * 4 + i) * 128 + k4 * 4];
#pragma unroll
            for (int dd = 0; dd < 4; ++dd) {
                const float* vr = &Vs[(k4 * 4 + dd) * 64];
                ulonglong2 va = *(const ulonglong2*)(vr + tx * 4);
#pragma unroll
                for (int i = 0; i < 4; ++i) {
                    ULL ap = pack2(GETC(p[i], dd));
                    fma2(o2[i][0], ap, va.x);
                    fma2(o2[i][1], ap, va.y);
                }
            }
        }
        __syncthreads();
    }

    // epilogue: normalize and write [b][t][h*64+d]
#pragma unroll
    for (int i = 0; i < 4; ++i) {
        float inv = 1.0f / li[i];
        float2 a = unpack2(o2[i][0]);
        float2 c = unpack2(o2[i][1]);
        int t = qt * 64 + ty * 4 + i;
        *(float4*)&g_att[((size_t)(bb * Tz + t)) * DIMz + h * 64 + tx * 4] =
            make_float4(a.x * inv, a.y * inv, c.x * inv, c.y * inv);
    }
}

// ---------------- Output projection (M=4096, N=1024, K=1024) + bias ----------------
__global__ __launch_bounds__(256, 2)
void proj_kernel(const float* __restrict__ W, const float* __restrict__ bias,
                 float* __restrict__ out) {
    __shared__ __align__(16) float As[2][128 * 16];
    __shared__ __align__(16) float Bs[2][16 * 128];
    const int tid = threadIdx.x;
    const int ty = tid >> 4, tx = tid & 15;
    const int m0 = blockIdx.y * 128;
    const int n0 = blockIdx.x * 128;

    const int rA0 = tid >> 2,          ksA0 = tid & 3;
    const int rA1 = (tid + 256) >> 2,  ksA1 = (tid + 256) & 3;
    const int kB0 = tid >> 5,          nsB0 = tid & 31;
    const int kB1 = (tid + 256) >> 5,  nsB1 = (tid + 256) & 31;

    ULL acc[8][4];
#pragma unroll
    for (int i = 0; i < 8; ++i)
#pragma unroll
        for (int j = 0; j < 4; ++j) acc[i][j] = 0ULL;

    {
        cp16(&As[0][rA0 * 16 + ksA0 * 4], &g_att[(size_t)(m0 + rA0) * 1024 + ksA0 * 4]);
        cp16(&As[0][rA1 * 16 + ksA1 * 4], &g_att[(size_t)(m0 + rA1) * 1024 + ksA1 * 4]);
        cp16(&Bs[0][kB0 * 128 + nsB0 * 4], &W[(size_t)kB0 * 1024 + n0 + nsB0 * 4]);
        cp16(&Bs[0][kB1 * 128 + nsB1 * 4], &W[(size_t)kB1 * 1024 + n0 + nsB1 * 4]);
        CP_COMMIT(); CP_WAIT0();
    }
    __syncthreads();

    for (int kt = 0; kt < 64; ++kt) {
        const int cur = kt & 1;
        if (kt < 63) {
            const int nxt = cur ^ 1;
            const int k0 = (kt + 1) * 16;
            cp16(&As[nxt][rA0 * 16 + ksA0 * 4], &g_att[(size_t)(m0 + rA0) * 1024 + k0 + ksA0 * 4]);
            cp16(&As[nxt][rA1 * 16 + ksA1 * 4], &g_att[(size_t)(m0 + rA1) * 1024 + k0 + ksA1 * 4]);
            cp16(&Bs[nxt][kB0 * 128 + nsB0 * 4], &W[(size_t)(k0 + kB0) * 1024 + n0 + nsB0 * 4]);
            cp16(&Bs[nxt][kB1 * 128 + nsB1 * 4], &W[(size_t)(k0 + kB1) * 1024 + n0 + nsB1 * 4]);
            CP_COMMIT();
        }
#pragma unroll
        for (int k4 = 0; k4 < 4; ++k4) {
            float4 a4[8];
#pragma unroll
            for (int i = 0; i < 8; ++i)
                a4[i] = *(const float4*)&As[cur][(ty * 8 + i) * 16 + k4 * 4];
#pragma unroll
            for (int dd = 0; dd < 4; ++dd) {
                const float* br = &Bs[cur][(k4 * 4 + dd) * 128];
                ulonglong2 u0 = *(const ulonglong2*)(br + tx * 4);
                ulonglong2 u1 = *(const ulonglong2*)(br + 64 + tx * 4);
#pragma unroll
                for (int i = 0; i < 8; ++i) {
                    ULL ap = pack2(GETC(a4[i], dd));
                    fma2(acc[i][0], ap, u0.x);
                    fma2(acc[i][1], ap, u0.y);
                    fma2(acc[i][2], ap, u1.x);
                    fma2(acc[i][3], ap, u1.y);
                }
            }
        }
        CP_WAIT0();
        __syncthreads();
    }

    float4 bi0 = *(const float4*)&bias[n0 + tx * 4];
    float4 bi1 = *(const float4*)&bias[n0 + 64 + tx * 4];
#pragma unroll
    for (int i = 0; i < 8; ++i) {
        int m = m0 + ty * 8 + i;
        float2 p0 = unpack2(acc[i][0]), p1 = unpack2(acc[i][1]);
        float2 p2 = unpack2(acc[i][2]), p3 = unpack2(acc[i][3]);
        *(float4*)&out[(size_t)m * 1024 + n0 + tx * 4] =
            make_float4(p0.x + bi0.x, p0.y + bi0.y, p1.x + bi0.z, p1.y + bi0.w);
        *(float4*)&out[(size_t)m * 1024 + n0 + 64 + tx * 4] =
            make_float4(p2.x + bi1.x, p2.y + bi1.y, p3.x + bi1.z, p3.y + bi1.w);
    }
}

// ---------------- launch ----------------
extern "C" void kernel_launch(void* const* d_in, const int* in_sizes, int n_in,
                              void* d_out, int out_size) {
    (void)in_sizes; (void)n_in; (void)out_size;
    const float* x    = (const float*)d_in[0];
    const float* Wqkv = (const float*)d_in[1];
    const float* Wout = (const float*)d_in[2];
    const float* bout = (const float*)d_in[3];
    float* out = (float*)d_out;

    cudaFuncSetAttribute(attn_kernel, cudaFuncAttributeMaxDynamicSharedMemorySize,
                         SM_FLOATS * (int)sizeof(float));

    rope_tables_kernel<<<(Tz * HDz) / 256, 256>>>();
    qkv_rope_kernel<<<dim3(N3z / 128, Mz / 128), 256>>>(x, Wqkv);
    attn_kernel<<<dim3(Tz / 64, Hz, Bz), 256, SM_FLOATS * (int)sizeof(float)>>>();
    proj_kernel<<<dim3(DIMz / 128, Mz / 128), 256>>>(Wout, bout, out);
}

// round 7
// speedup vs baseline: 1.5148x; 1.4213x over previous
#include <cuda_runtime.h>
#include <cuda_bf16.h>

#define Bz   2
#define Tz   2048
#define DIMz 1024
#define Hz   16
#define HDz  64
#define Mz   (Bz*Tz)      /* 4096 */
#define N3z  (3*DIMz)     /* 3072 */

typedef unsigned long long ULL;

// ---------------- scratch (device globals: allocation-free) ----------------
__device__ float g_q  [Bz*Hz*Tz*HDz];   // [b][h][t][d]
__device__ float g_kT [Bz*Hz*HDz*Tz];   // [b][h][d][t]
__device__ float g_v  [Bz*Hz*Tz*HDz];   // [b][h][t][d]
__device__ float g_att[Mz*DIMz];        // [b*t][dim]
__device__ float g_cos[Tz*HDz];
__device__ float g_sin[Tz*HDz];

// fragment-order bf16 hi/lo operands (16B chunks)
__device__ uint4 g_xhi [ (Mz/16)*(DIMz/16)*32 ];    // 524288
__device__ uint4 g_xlo [ (Mz/16)*(DIMz/16)*32 ];
__device__ uint4 g_wqh [ (DIMz/16)*(N3z/16)*32 ];   // 393216
__device__ uint4 g_wql [ (DIMz/16)*(N3z/16)*32 ];
__device__ uint4 g_woh [ (DIMz/16)*(DIMz/16)*32 ];  // 131072
__device__ uint4 g_wol [ (DIMz/16)*(DIMz/16)*32 ];
__device__ uint4 g_athi[ (Mz/16)*(DIMz/16)*32 ];
__device__ uint4 g_atlo[ (Mz/16)*(DIMz/16)*32 ];

// ---------------- f32x2 packed helpers (attention kernel) ----------------
__device__ __forceinline__ ULL pack2(float x) {
    ULL r; unsigned u = __float_as_uint(x);
    asm("mov.b64 %0, {%1, %1};" : "=l"(r) : "r"(u));
    return r;
}
__device__ __forceinline__ void fma2(ULL &d, ULL a, ULL b) {
    asm("fma.rn.f32x2 %0, %1, %2, %0;" : "+l"(d) : "l"(a), "l"(b));
}
__device__ __forceinline__ void mul2(ULL &d, ULL a) {
    asm("mul.rn.f32x2 %0, %0, %1;" : "+l"(d) : "l"(a));
}
__device__ __forceinline__ float2 unpack2(ULL v) {
    float2 r;
    r.x = __uint_as_float((unsigned)v);
    r.y = __uint_as_float((unsigned)(v >> 32));
    return r;
}
#define GETC(f4, dd) ((dd)==0 ? (f4).x : (dd)==1 ? (f4).y : (dd)==2 ? (f4).z : (f4).w)

// ---------------- cp.async helpers ----------------
__device__ __forceinline__ void cp16(void* dst, const void* src) {
    unsigned d = (unsigned)__cvta_generic_to_shared(dst);
    asm volatile("cp.async.cg.shared.global [%0], [%1], 16;" :: "r"(d), "l"(src));
}
#define CP_COMMIT() asm volatile("cp.async.commit_group;")
#define CP_WAIT0()  asm volatile("cp.async.wait_group 0;")

// ---------------- MMA helper: m16n8k16 bf16 -> f32 ----------------
__device__ __forceinline__ void mma_bf16(float* c, const uint4& a, unsigned b0, unsigned b1) {
    asm("mma.sync.aligned.m16n8k16.row.col.f32.bf16.bf16.f32 "
        "{%0,%1,%2,%3}, {%4,%5,%6,%7}, {%8,%9}, {%0,%1,%2,%3};"
        : "+f"(c[0]), "+f"(c[1]), "+f"(c[2]), "+f"(c[3])
        : "r"(a.x), "r"(a.y), "r"(a.z), "r"(a.w), "r"(b0), "r"(b1));
}

__device__ __forceinline__ unsigned pkbf(float x, float y) {
    __nv_bfloat162 h = __floats2bfloat162_rn(x, y);
    return *reinterpret_cast<unsigned*>(&h);
}

// ---------------- RoPE cos/sin tables ----------------
__global__ void rope_tables_kernel() {
    int idx = blockIdx.x * 256 + threadIdx.x;
    int t = idx >> 6, d = idx & 63;
    float inv = expf(-(float)(d & 31) * (9.210340371976184f / 32.0f));
    float ang = (float)t * inv;
    g_cos[idx] = cosf(ang);
    g_sin[idx] = sinf(ang);
}

// ---------------- prep: fp32 matrix -> frag-order bf16 hi/lo ----------------
// A-order (M x K, row-major source). Tile (16x16): 32 lanes x 16B.
// lane L: g=L/4, i=L%4; slot s: row = g+8*(s&1), k = 2i+8*(s>>1)+{0,1}.
__device__ __forceinline__ void prepA_body(const float* __restrict__ src,
                                           uint4* __restrict__ dhi, uint4* __restrict__ dlo,
                                           int Kt, int gid) {
    int L = gid & 31, at = gid >> 5;
    int mt = at / Kt, kt = at - mt * Kt;
    int g = L >> 2, i = L & 3;
    const int K = Kt * 16;
    unsigned uh[4], ul[4];
#pragma unroll
    for (int s = 0; s < 4; ++s) {
        int row = mt * 16 + g + 8 * (s & 1);
        int k   = kt * 16 + 2 * i + 8 * (s >> 1);
        float2 f = *(const float2*)(src + (size_t)row * K + k);
        float h0 = __bfloat162float(__float2bfloat16(f.x));
        float h1 = __bfloat162float(__float2bfloat16(f.y));
        uh[s] = pkbf(f.x, f.y);
        ul[s] = pkbf(f.x - h0, f.y - h1);
    }
    size_t d = (size_t)at * 32 + L;
    dhi[d] = make_uint4(uh[0], uh[1], uh[2], uh[3]);
    dlo[d] = make_uint4(ul[0], ul[1], ul[2], ul[3]);
}

// B-order (K x N, row-major source). Tile (16 k x 16 n) packs two n8 tiles.
// lane L: g=L/4, i=L%4; slot s: k = 2i+8*(s&1)+{0,1}, col = g+8*(s>>1).
__device__ __forceinline__ void prepB_body(const float* __restrict__ src,
                                           uint4* __restrict__ dhi, uint4* __restrict__ dlo,
                                           int Nt, int N, int gid) {
    int L = gid & 31, bt = gid >> 5;
    int kt = bt / Nt, nt = bt - kt * Nt;
    int g = L >> 2, i = L & 3;
    unsigned uh[4], ul[4];
#pragma unroll
    for (int s = 0; s < 4; ++s) {
        int k   = kt * 16 + 2 * i + 8 * (s & 1);
        int col = nt * 16 + g + 8 * (s >> 1);
        float f0 = src[(size_t)k * N + col];
        float f1 = src[(size_t)(k + 1) * N + col];
        float h0 = __bfloat162float(__float2bfloat16(f0));
        float h1 = __bfloat162float(__float2bfloat16(f1));
        uh[s] = pkbf(f0, f1);
        ul[s] = pkbf(f0 - h0, f1 - h1);
    }
    size_t d = (size_t)bt * 32 + L;
    dhi[d] = make_uint4(uh[0], uh[1], uh[2], uh[3]);
    dlo[d] = make_uint4(ul[0], ul[1], ul[2], ul[3]);
}

__global__ void prep_x_kernel(const float* __restrict__ src) {
    prepA_body(src, g_xhi, g_xlo, DIMz / 16, blockIdx.x * 256 + threadIdx.x);
}
__global__ void prep_att_kernel() {
    prepA_body(g_att, g_athi, g_atlo, DIMz / 16, blockIdx.x * 256 + threadIdx.x);
}
__global__ void prep_wq_kernel(const float* __restrict__ src) {
    prepB_body(src, g_wqh, g_wql, N3z / 16, N3z, blockIdx.x * 256 + threadIdx.x);
}
__global__ void prep_wo_kernel(const float* __restrict__ src) {
    prepB_body(src, g_woh, g_wol, DIMz / 16, DIMz, blockIdx.x * 256 + threadIdx.x);
}

// ---------------- split-bf16 HMMA GEMM cores ----------------
// 128x128 block, 8 warps (2 M x 4 N), warp tile 64x32.
// smem stage (16B units): Ahi[0,512) Alo[512,1024) Bhi[1024,1536) Blo[1536,2048).
// A chunk: (mtLocal*2+kt)*32+L ; B chunk: (kt*8+ntLocal)*32+L.
#define GEMM_SMEM_BYTES (2 * 2048 * 16)

#define GEMM_MAIN(AHI, ALO, BHI, BLO, NT16TOT)                                           \
    extern __shared__ uint4 sm4[];                                                        \
    const int tid = threadIdx.x;                                                          \
    const int L = tid & 31, warp = tid >> 5;                                              \
    const int wm = warp >> 2, wn = warp & 3;                                              \
    const int g = L >> 2, i = L & 3;                                                      \
    const int mt0 = blockIdx.y * 8, nt0 = blockIdx.x * 8;                                 \
    float acc[4][4][4];                                                                   \
    _Pragma("unroll")                                                                     \
    for (int a = 0; a < 4; ++a)                                                           \
        _Pragma("unroll")                                                                 \
        for (int b = 0; b < 4; ++b)                                                       \
            _Pragma("unroll")                                                             \
            for (int c = 0; c < 4; ++c) acc[a][b][c] = 0.f;                               \
    /* prologue: stage 0 */                                                               \
    _Pragma("unroll")                                                                     \
    for (int c = 0; c < 2; ++c) {                                                         \
        int e = tid + c * 256;                                                            \
        int mt = e >> 6, kt = (e >> 5) & 1, l = e & 31;                                   \
        size_t s = ((size_t)(mt0 + mt) * 64 + kt) * 32 + l;                               \
        cp16(&sm4[(mt * 2 + kt) * 32 + l], &AHI[s]);                                      \
        cp16(&sm4[512 + (mt * 2 + kt) * 32 + l], &ALO[s]);                                \
    }                                                                                     \
    _Pragma("unroll")                                                                     \
    for (int c = 0; c < 2; ++c) {                                                         \
        int e = tid + c * 256;                                                            \
        int kt = e >> 8, nt = (e >> 5) & 7, l = e & 31;                                   \
        size_t s = ((size_t)kt * NT16TOT + nt0 + nt) * 32 + l;                            \
        cp16(&sm4[1024 + (kt * 8 + nt) * 32 + l], &BHI[s]);                               \
        cp16(&sm4[1536 + (kt * 8 + nt) * 32 + l], &BLO[s]);                               \
    }                                                                                     \
    CP_COMMIT(); CP_WAIT0();                                                              \
    __syncthreads();                                                                      \
    for (int st = 0; st < 32; ++st) {                                                     \
        const int cur = st & 1;                                                           \
        const int sb = cur * 2048;                                                        \
        if (st < 31) {                                                                    \
            const int nb = (cur ^ 1) * 2048;                                              \
            const int kg = (st + 1) * 2;                                                  \
            _Pragma("unroll")                                                             \
            for (int c = 0; c < 2; ++c) {                                                 \
                int e = tid + c * 256;                                                    \
                int mt = e >> 6, kt = (e >> 5) & 1, l = e & 31;                           \
                size_t s = ((size_t)(mt0 + mt) * 64 + kg + kt) * 32 + l;                  \
                cp16(&sm4[nb + (mt * 2 + kt) * 32 + l], &AHI[s]);                         \
                cp16(&sm4[nb + 512 + (mt * 2 + kt) * 32 + l], &ALO[s]);                   \
            }                                                                             \
            _Pragma("unroll")                                                             \
            for (int c = 0; c < 2; ++c) {                                                 \
                int e = tid + c * 256;                                                    \
                int kt = e >> 8, nt = (e >> 5) & 7, l = e & 31;                           \
                size_t s = ((size_t)(kg + kt) * NT16TOT + nt0 + nt) * 32 + l;             \
                cp16(&sm4[nb + 1024 + (kt * 8 + nt) * 32 + l], &BHI[s]);                  \
                cp16(&sm4[nb + 1536 + (kt * 8 + nt) * 32 + l], &BLO[s]);                  \
            }                                                                             \
            CP_COMMIT();                                                                  \
        }                                                                                 \
        _Pragma("unroll")                                                                 \
        for (int kt = 0; kt < 2; ++kt) {                                                  \
            uint4 ah[4], al[4], bh[2], bl[2];                                             \
            _Pragma("unroll")                                                             \
            for (int mt = 0; mt < 4; ++mt) {                                              \
                int idx = ((wm * 4 + mt) * 2 + kt) * 32 + L;                              \
                ah[mt] = sm4[sb + idx];                                                   \
                al[mt] = sm4[sb + 512 + idx];                                             \
            }                                                                             \
            _Pragma("unroll")                                                             \
            for (int nt = 0; nt < 2; ++nt) {                                              \
                int idx = (kt * 8 + wn * 2 + nt) * 32 + L;                                \
                bh[nt] = sm4[sb + 1024 + idx];                                            \
                bl[nt] = sm4[sb + 1536 + idx];                                            \
            }                                                                             \
            _Pragma("unroll")                                                             \
            for (int mt = 0; mt < 4; ++mt)                                                \
                _Pragma("unroll")                                                         \
                for (int nt = 0; nt < 2; ++nt) {                                          \
                    float* c0 = acc[mt][nt * 2];                                          \
                    float* c1 = acc[mt][nt * 2 + 1];                                      \
                    mma_bf16(c0, ah[mt], bh[nt].x, bh[nt].y);                             \
                    mma_bf16(c1, ah[mt], bh[nt].z, bh[nt].w);                             \
                    mma_bf16(c0, ah[mt], bl[nt].x, bl[nt].y);                             \
                    mma_bf16(c1, ah[mt], bl[nt].z, bl[nt].w);                             \
                    mma_bf16(c0, al[mt], bh[nt].x, bh[nt].y);                             \
                    mma_bf16(c1, al[mt], bh[nt].z, bh[nt].w);                             \
                }                                                                         \
        }                                                                                 \
        if (st < 31) CP_WAIT0();                                                          \
        __syncthreads();                                                                  \
    }

// ---- QKV GEMM + RoPE epilogue ----
__global__ __launch_bounds__(256)
void qkv_mma_kernel() {
    GEMM_MAIN(g_xhi, g_xlo, g_wqh, g_wql, 192)

    const int n0 = blockIdx.x * 128;
    const int m0 = blockIdx.y * 128;
    const int which = n0 >> 10;
    const int bbb = m0 >> 11;
    const int hh = ((n0 & 1023) >> 6) + (wn >> 1);

#pragma unroll
    for (int mt = 0; mt < 4; ++mt) {
#pragma unroll
        for (int nt = 0; nt < 2; ++nt) {
#pragma unroll
            for (int n8 = 0; n8 < 2; ++n8) {
                const float* c = acc[mt][nt * 2 + n8];
                int d0 = (wn & 1) * 32 + nt * 16 + n8 * 8 + 2 * i;
#pragma unroll
                for (int half = 0; half < 2; ++half) {
                    int t = (m0 & 2047) + wm * 64 + mt * 16 + g + 8 * half;
                    float v0 = c[half * 2], v1 = c[half * 2 + 1];
                    if (which == 2) {
                        *(float2*)&g_v[(((size_t)(bbb * Hz + hh) * Tz + t) * HDz) + d0] =
                            make_float2(v0, v1);
                    } else {
                        float2 cs = *(const float2*)&g_cos[t * 64 + d0];
                        float2 sn = *(const float2*)&g_sin[t * 64 + d0];
                        float re = v0 * cs.x - v1 * sn.x;
                        float ro = v1 * cs.y + v0 * sn.y;
                        if (which == 0) {
                            *(float2*)&g_q[(((size_t)(bbb * Hz + hh) * Tz + t) * HDz) + d0] =
                                make_float2(re, ro);
                        } else {
                            size_t base = ((size_t)(bbb * Hz + hh) * HDz + d0) * Tz + t;
                            g_kT[base] = re;
                            g_kT[base + Tz] = ro;
                        }
                    }
                }
            }
        }
    }
}

// ---- Output projection + bias ----
__global__ __launch_bounds__(256)
void proj_mma_kernel(const float* __restrict__ bias, float* __restrict__ out) {
    GEMM_MAIN(g_athi, g_atlo, g_woh, g_wol, 64)

    const int n0 = blockIdx.x * 128;
    const int m0 = blockIdx.y * 128;

#pragma unroll
    for (int mt = 0; mt < 4; ++mt) {
#pragma unroll
        for (int nt = 0; nt < 2; ++nt) {
#pragma unroll
            for (int n8 = 0; n8 < 2; ++n8) {
                const float* c = acc[mt][nt * 2 + n8];
                int col = n0 + wn * 32 + nt * 16 + n8 * 8 + 2 * i;
                float2 bi = *(const float2*)&bias[col];
#pragma unroll
                for (int half = 0; half < 2; ++half) {
                    int m = m0 + wm * 64 + mt * 16 + g + 8 * half;
                    *(float2*)&out[(size_t)m * 1024 + col] =
                        make_float2(c[half * 2] + bi.x, c[half * 2 + 1] + bi.y);
                }
            }
        }
    }
}

// ---------------- Flash attention (unchanged f32x2 SIMT, Tq=64 x Tk=128) ----------------
#define SM_QS 0
#define SM_KS 4096
#define SM_VS (4096 + 8192)
#define SM_PS (4096 + 16384)
#define SM_FLOATS (4096 + 8192 + 8192 + 8192)

__global__ __launch_bounds__(256, 2)
void attn_kernel() {
    extern __shared__ __align__(16) float sm[];
    float* Qs = sm + SM_QS;
    float* Ks = sm + SM_KS;
    float* Vs = sm + SM_VS;
    float* Ps = sm + SM_PS;

    const int tid = threadIdx.x;
    const int ty = tid >> 4, tx = tid & 15;
    const int qt = blockIdx.x, h = blockIdx.y, bb = blockIdx.z;

    const float* Qg = g_q  + ((size_t)(bb * Hz + h) * Tz + qt * 64) * HDz;
    const float* Kg = g_kT + (size_t)(bb * Hz + h) * HDz * Tz;
    const float* Vg = g_v  + (size_t)(bb * Hz + h) * Tz * HDz;

#pragma unroll
    for (int s = 0; s < 4; ++s) {
        int e = tid + s * 256;
        int r = e >> 4, seg = e & 15;
        float4 v = *(const float4*)&Qg[r * HDz + seg * 4];
        v.x *= 0.125f; v.y *= 0.125f; v.z *= 0.125f; v.w *= 0.125f;
        *(float4*)&Qs[r * 64 + seg * 4] = v;
    }

    ULL o2[4][2];
    float mi[4], li[4];
#pragma unroll
    for (int ii = 0; ii < 4; ++ii) { o2[ii][0] = 0; o2[ii][1] = 0; mi[ii] = -1e30f; li[ii] = 0.f; }
    __syncthreads();

    for (int kt = 0; kt < 16; ++kt) {
#pragma unroll
        for (int s = 0; s < 8; ++s) {
            int e = tid + s * 256;
            int d = e >> 5, seg = e & 31;
            *(float4*)&Ks[d * 128 + seg * 4] =
                *(const float4*)&Kg[(size_t)d * Tz + kt * 128 + seg * 4];
        }
#pragma unroll
        for (int s = 0; s < 8; ++s) {
            int e = tid + s * 256;
            int k = e >> 4, seg = e & 15;
            *(float4*)&Vs[k * 64 + seg * 4] =
                *(const float4*)&Vg[(size_t)(kt * 128 + k) * HDz + seg * 4];
        }
        __syncthreads();

        ULL s2[4][4];
#pragma unroll
        for (int ii = 0; ii < 4; ++ii)
#pragma unroll
            for (int j = 0; j < 4; ++j) s2[ii][j] = 0ULL;

#pragma unroll 4
        for (int d4 = 0; d4 < 16; ++d4) {
            float4 q[4];
#pragma unroll
            for (int ii = 0; ii < 4; ++ii)
                q[ii] = *(const float4*)&Qs[(ty * 4 + ii) * 64 + d4 * 4];
#pragma unroll
            for (int dd = 0; dd < 4; ++dd) {
                const float* kr = &Ks[(d4 * 4 + dd) * 128];
                ulonglong2 ka = *(const ulonglong2*)(kr + tx * 4);
                ulonglong2 kb = *(const ulonglong2*)(kr + 64 + tx * 4);
#pragma unroll
                for (int ii = 0; ii < 4; ++ii) {
                    ULL ap = pack2(GETC(q[ii], dd));
                    fma2(s2[ii][0], ap, ka.x);
                    fma2(s2[ii][1], ap, ka.y);
                    fma2(s2[ii][2], ap, kb.x);
                    fma2(s2[ii][3], ap, kb.y);
                }
            }
        }

#pragma unroll
        for (int ii = 0; ii < 4; ++ii) {
            float2 sa = unpack2(s2[ii][0]), sb = unpack2(s2[ii][1]);
            float2 sc = unpack2(s2[ii][2]), sd = unpack2(s2[ii][3]);
            float v0 = sa.x, v1 = sa.y, v2 = sb.x, v3 = sb.y;
            float v4 = sc.x, v5 = sc.y, v6 = sd.x, v7 = sd.y;
            float mx = fmaxf(fmaxf(fmaxf(v0, v1), fmaxf(v2, v3)),
                             fmaxf(fmaxf(v4, v5), fmaxf(v6, v7)));
            mx = fmaxf(mx, __shfl_xor_sync(0xffffffffu, mx, 1));
            mx = fmaxf(mx, __shfl_xor_sync(0xffffffffu, mx, 2));
            mx = fmaxf(mx, __shfl_xor_sync(0xffffffffu, mx, 4));
            mx = fmaxf(mx, __shfl_xor_sync(0xffffffffu, mx, 8));
            float mnew = fmaxf(mi[ii], mx);
            float f = __expf(mi[ii] - mnew);
            mi[ii] = mnew;
            float p0 = __expf(v0 - mnew), p1 = __expf(v1 - mnew);
            float p2 = __expf(v2 - mnew), p3 = __expf(v3 - mnew);
            float p4 = __expf(v4 - mnew), p5 = __expf(v5 - mnew);
            float p6 = __expf(v6 - mnew), p7 = __expf(v7 - mnew);
            float ls = (p0 + p1) + (p2 + p3) + (p4 + p5) + (p6 + p7);
            ls += __shfl_xor_sync(0xffffffffu, ls, 1);
            ls += __shfl_xor_sync(0xffffffffu, ls, 2);
            ls += __shfl_xor_sync(0xffffffffu, ls, 4);
            ls += __shfl_xor_sync(0xffffffffu, ls, 8);
            li[ii] = li[ii] * f + ls;
            ULL f2 = pack2(f);
            mul2(o2[ii][0], f2);
            mul2(o2[ii][1], f2);
            *(float4*)&Ps[(ty * 4 + ii) * 128 + tx * 4]      = make_float4(p0, p1, p2, p3);
            *(float4*)&Ps[(ty * 4 + ii) * 128 + 64 + tx * 4] = make_float4(p4, p5, p6, p7);
        }
        __syncthreads();

#pragma unroll 4
        for (int k4 = 0; k4 < 32; ++k4) {
            float4 p[4];
#pragma unroll
            for (int ii = 0; ii < 4; ++ii)
                p[ii] = *(const float4*)&Ps[(ty * 4 + ii) * 128 + k4 * 4];
#pragma unroll
            for (int dd = 0; dd < 4; ++dd) {
                const float* vr = &Vs[(k4 * 4 + dd) * 64];
                ulonglong2 va = *(const ulonglong2*)(vr + tx * 4);
#pragma unroll
                for (int ii = 0; ii < 4; ++ii) {
                    ULL ap = pack2(GETC(p[ii], dd));
                    fma2(o2[ii][0], ap, va.x);
                    fma2(o2[ii][1], ap, va.y);
                }
            }
        }
        __syncthreads();
    }

#pragma unroll
    for (int ii = 0; ii < 4; ++ii) {
        float inv = 1.0f / li[ii];
        float2 a = unpack2(o2[ii][0]);
        float2 c = unpack2(o2[ii][1]);
        int t = qt * 64 + ty * 4 + ii;
        *(float4*)&g_att[((size_t)(bb * Tz + t)) * DIMz + h * 64 + tx * 4] =
            make_float4(a.x * inv, a.y * inv, c.x * inv, c.y * inv);
    }
}

// ---------------- launch ----------------
extern "C" void kernel_launch(void* const* d_in, const int* in_sizes, int n_in,
                              void* d_out, int out_size) {
    (void)in_sizes; (void)n_in; (void)out_size;
    const float* x    = (const float*)d_in[0];
    const float* Wqkv = (const float*)d_in[1];
    const float* Wout = (const float*)d_in[2];
    const float* bout = (const float*)d_in[3];
    float* out = (float*)d_out;

    cudaFuncSetAttribute(attn_kernel, cudaFuncAttributeMaxDynamicSharedMemorySize,
                         SM_FLOATS * (int)sizeof(float));
    cudaFuncSetAttribute(qkv_mma_kernel, cudaFuncAttributeMaxDynamicSharedMemorySize,
                         GEMM_SMEM_BYTES);
    cudaFuncSetAttribute(proj_mma_kernel, cudaFuncAttributeMaxDynamicSharedMemorySize,
                         GEMM_SMEM_BYTES);

    rope_tables_kernel<<<(Tz * HDz) / 256, 256>>>();
    prep_x_kernel <<<(Mz/16)*(DIMz/16)*32/256, 256>>>(x);
    prep_wq_kernel<<<(DIMz/16)*(N3z/16)*32/256, 256>>>(Wqkv);
    prep_wo_kernel<<<(DIMz/16)*(DIMz/16)*32/256, 256>>>(Wout);

    qkv_mma_kernel<<<dim3(N3z / 128, Mz / 128), 256, GEMM_SMEM_BYTES>>>();
    attn_kernel<<<dim3(Tz / 64, Hz, Bz), 256, SM_FLOATS * (int)sizeof(float)>>>();
    prep_att_kernel<<<(Mz/16)*(DIMz/16)*32/256, 256>>>();
    proj_mma_kernel<<<dim3(DIMz / 128, Mz / 128), 256, GEMM_SMEM_BYTES>>>(bout, out);
}

// round 8
// speedup vs baseline: 2.4383x; 1.6097x over previous
#include <cuda_runtime.h>
#include <cuda_bf16.h>

#define Bz   2
#define Tz   2048
#define DIMz 1024
#define Hz   16
#define HDz  64
#define Mz   (Bz*Tz)      /* 4096 */
#define N3z  (3*DIMz)     /* 3072 */

// scale folded into Q fragments: (1/8) * log2(e)
#define QSCALE 0.18033688011112042f

// ---------------- scratch (device globals: allocation-free) ----------------
__device__ float g_q  [Bz*Hz*Tz*HDz];   // [bh][t][d]  (RoPE'd, pre-scaled? no: raw)
__device__ float g_k  [Bz*Hz*Tz*HDz];   // [bh][t][d]  (RoPE'd)
__device__ float g_v  [Bz*Hz*Tz*HDz];   // [bh][t][d]
__device__ float g_att[Mz*DIMz];        // [b*t][dim]
__device__ float g_cos[Tz*HDz];
__device__ float g_sin[Tz*HDz];

// fragment-order bf16 hi/lo operands (16B chunks)
__device__ uint4 g_xhi [ (Mz/16)*(DIMz/16)*32 ];
__device__ uint4 g_xlo [ (Mz/16)*(DIMz/16)*32 ];
__device__ uint4 g_wqh [ (DIMz/16)*(N3z/16)*32 ];
__device__ uint4 g_wql [ (DIMz/16)*(N3z/16)*32 ];
__device__ uint4 g_woh [ (DIMz/16)*(DIMz/16)*32 ];
__device__ uint4 g_wol [ (DIMz/16)*(DIMz/16)*32 ];
__device__ uint4 g_athi[ (Mz/16)*(DIMz/16)*32 ];
__device__ uint4 g_atlo[ (Mz/16)*(DIMz/16)*32 ];

// attention fragment arrays: per bh, 128 16-tiles x 4 16-steps x 32 lanes
#define BH_FRAG (128*4*32)
__device__ uint4 g_qfh[32*BH_FRAG];   // Q A-frags (row=t, k=d), scaled by QSCALE
__device__ uint4 g_qfl[32*BH_FRAG];
__device__ uint4 g_kfh[32*BH_FRAG];   // K B-frags (k=d contraction, col=t)
__device__ uint4 g_kfl[32*BH_FRAG];
__device__ uint4 g_vfh[32*BH_FRAG];   // V B-frags (k=t contraction, col=d)
__device__ uint4 g_vfl[32*BH_FRAG];

// ---------------- helpers ----------------
__device__ __forceinline__ void cp16(void* dst, const void* src) {
    unsigned d = (unsigned)__cvta_generic_to_shared(dst);
    asm volatile("cp.async.cg.shared.global [%0], [%1], 16;" :: "r"(d), "l"(src));
}
#define CP_COMMIT() asm volatile("cp.async.commit_group;")
#define CP_WAIT0()  asm volatile("cp.async.wait_group 0;")

__device__ __forceinline__ void mma_bf16(float* c, const uint4& a, unsigned b0, unsigned b1) {
    asm("mma.sync.aligned.m16n8k16.row.col.f32.bf16.bf16.f32 "
        "{%0,%1,%2,%3}, {%4,%5,%6,%7}, {%8,%9}, {%0,%1,%2,%3};"
        : "+f"(c[0]), "+f"(c[1]), "+f"(c[2]), "+f"(c[3])
        : "r"(a.x), "r"(a.y), "r"(a.z), "r"(a.w), "r"(b0), "r"(b1));
}

__device__ __forceinline__ unsigned pkbf(float x, float y) {
    __nv_bfloat162 h = __floats2bfloat162_rn(x, y);
    return *reinterpret_cast<unsigned*>(&h);
}

// fast 2^z for z <= 0 on FMA/ALU pipes (error < 3e-6 rel)
__device__ __forceinline__ float exp2p(float z) {
    z = fmaxf(z, -120.f);
    float fn = rintf(z);
    float r = z - fn;
    int n = (int)fn;
    float p = 0.0013333558146428443f;
    p = fmaf(p, r, 0.009618129107628477f);
    p = fmaf(p, r, 0.05550410866482158f);
    p = fmaf(p, r, 0.24022650695910072f);
    p = fmaf(p, r, 0.6931471805599453f);
    p = fmaf(p, r, 1.0f);
    return __int_as_float(__float_as_int(p) + (n << 23));
}

// ---------------- RoPE cos/sin tables ----------------
__global__ void rope_tables_kernel() {
    int idx = blockIdx.x * 256 + threadIdx.x;
    int t = idx >> 6, d = idx & 63;
    float inv = expf(-(float)(d & 31) * (9.210340371976184f / 32.0f));
    float ang = (float)t * inv;
    g_cos[idx] = cosf(ang);
    g_sin[idx] = sinf(ang);
}

// ---------------- prep: fp32 matrix -> frag-order bf16 hi/lo (dense GEMMs) --------
__device__ __forceinline__ void prepA_body(const float* __restrict__ src,
                                           uint4* __restrict__ dhi, uint4* __restrict__ dlo,
                                           int Kt, int gid) {
    int L = gid & 31, at = gid >> 5;
    int mt = at / Kt, kt = at - mt * Kt;
    int g = L >> 2, i = L & 3;
    const int K = Kt * 16;
    unsigned uh[4], ul[4];
#pragma unroll
    for (int s = 0; s < 4; ++s) {
        int row = mt * 16 + g + 8 * (s & 1);
        int k   = kt * 16 + 2 * i + 8 * (s >> 1);
        float2 f = *(const float2*)(src + (size_t)row * K + k);
        float h0 = __bfloat162float(__float2bfloat16(f.x));
        float h1 = __bfloat162float(__float2bfloat16(f.y));
        uh[s] = pkbf(f.x, f.y);
        ul[s] = pkbf(f.x - h0, f.y - h1);
    }
    size_t d = (size_t)at * 32 + L;
    dhi[d] = make_uint4(uh[0], uh[1], uh[2], uh[3]);
    dlo[d] = make_uint4(ul[0], ul[1], ul[2], ul[3]);
}

__device__ __forceinline__ void prepB_body(const float* __restrict__ src,
                                           uint4* __restrict__ dhi, uint4* __restrict__ dlo,
                                           int Nt, int N, int gid) {
    int L = gid & 31, bt = gid >> 5;
    int kt = bt / Nt, nt = bt - kt * Nt;
    int g = L >> 2, i = L & 3;
    unsigned uh[4], ul[4];
#pragma unroll
    for (int s = 0; s < 4; ++s) {
        int k   = kt * 16 + 2 * i + 8 * (s & 1);
        int col = nt * 16 + g + 8 * (s >> 1);
        float f0 = src[(size_t)k * N + col];
        float f1 = src[(size_t)(k + 1) * N + col];
        float h0 = __bfloat162float(__float2bfloat16(f0));
        float h1 = __bfloat162float(__float2bfloat16(f1));
        uh[s] = pkbf(f0, f1);
        ul[s] = pkbf(f0 - h0, f1 - h1);
    }
    size_t d = (size_t)bt * 32 + L;
    dhi[d] = make_uint4(uh[0], uh[1], uh[2], uh[3]);
    dlo[d] = make_uint4(ul[0], ul[1], ul[2], ul[3]);
}

__global__ void prep_x_kernel(const float* __restrict__ src) {
    prepA_body(src, g_xhi, g_xlo, DIMz / 16, blockIdx.x * 256 + threadIdx.x);
}
__global__ void prep_att_kernel() {
    prepA_body(g_att, g_athi, g_atlo, DIMz / 16, blockIdx.x * 256 + threadIdx.x);
}
__global__ void prep_wq_kernel(const float* __restrict__ src) {
    prepB_body(src, g_wqh, g_wql, N3z / 16, N3z, blockIdx.x * 256 + threadIdx.x);
}
__global__ void prep_wo_kernel(const float* __restrict__ src) {
    prepB_body(src, g_woh, g_wol, DIMz / 16, DIMz, blockIdx.x * 256 + threadIdx.x);
}

// ---------------- prep: attention Q/K/V fp32 -> frag order hi/lo ----------------
// 131072 threads each (32 bh x 128 tiles x 32 lanes); each handles 4 16-steps.
__global__ void prep_qf_kernel() {
    int gid = blockIdx.x * 256 + threadIdx.x;
    int L = gid & 31, rest = gid >> 5;
    int mt = rest & 127, bh = rest >> 7;
    int g = L >> 2, i = L & 3;
    const float* src = g_q + (size_t)bh * Tz * HDz;
#pragma unroll
    for (int ds = 0; ds < 4; ++ds) {
        unsigned uh[4], ul[4];
#pragma unroll
        for (int s = 0; s < 4; ++s) {
            int row = mt * 16 + g + 8 * (s & 1);
            int k   = ds * 16 + 2 * i + 8 * (s >> 1);
            float2 f = *(const float2*)(src + row * 64 + k);
            f.x *= QSCALE; f.y *= QSCALE;
            float h0 = __bfloat162float(__float2bfloat16(f.x));
            float h1 = __bfloat162float(__float2bfloat16(f.y));
            uh[s] = pkbf(f.x, f.y);
            ul[s] = pkbf(f.x - h0, f.y - h1);
        }
        size_t d = ((size_t)(bh * 128 + mt) * 4 + ds) * 32 + L;
        g_qfh[d] = make_uint4(uh[0], uh[1], uh[2], uh[3]);
        g_qfl[d] = make_uint4(ul[0], ul[1], ul[2], ul[3]);
    }
}

__global__ void prep_kf_kernel() {
    int gid = blockIdx.x * 256 + threadIdx.x;
    int L = gid & 31, rest = gid >> 5;
    int nt = rest & 127, bh = rest >> 7;
    int g = L >> 2, i = L & 3;
    const float* src = g_k + (size_t)bh * Tz * HDz;
#pragma unroll
    for (int ds = 0; ds < 4; ++ds) {
        unsigned uh[4], ul[4];
#pragma unroll
        for (int s = 0; s < 4; ++s) {
            int k   = ds * 16 + 2 * i + 8 * (s & 1);      // d (contraction)
            int col = nt * 16 + g + 8 * (s >> 1);         // t
            float2 f = *(const float2*)(src + col * 64 + k);
            float h0 = __bfloat162float(__float2bfloat16(f.x));
            float h1 = __bfloat162float(__float2bfloat16(f.y));
            uh[s] = pkbf(f.x, f.y);
            ul[s] = pkbf(f.x - h0, f.y - h1);
        }
        size_t d = ((size_t)(bh * 128 + nt) * 4 + ds) * 32 + L;
        g_kfh[d] = make_uint4(uh[0], uh[1], uh[2], uh[3]);
        g_kfl[d] = make_uint4(ul[0], ul[1], ul[2], ul[3]);
    }
}

__global__ void prep_vf_kernel() {
    int gid = blockIdx.x * 256 + threadIdx.x;
    int L = gid & 31, rest = gid >> 5;
    int tt = rest & 127, bh = rest >> 7;
    int g = L >> 2, i = L & 3;
    const float* src = g_v + (size_t)bh * Tz * HDz;
#pragma unroll
    for (int d16 = 0; d16 < 4; ++d16) {
        unsigned uh[4], ul[4];
#pragma unroll
        for (int s = 0; s < 4; ++s) {
            int k   = tt * 16 + 2 * i + 8 * (s & 1);      // t (contraction)
            int col = d16 * 16 + g + 8 * (s >> 1);        // d
            float f0 = src[(size_t)k * 64 + col];
            float f1 = src[(size_t)(k + 1) * 64 + col];
            float h0 = __bfloat162float(__float2bfloat16(f0));
            float h1 = __bfloat162float(__float2bfloat16(f1));
            uh[s] = pkbf(f0, f1);
            ul[s] = pkbf(f0 - h0, f1 - h1);
        }
        size_t d = ((size_t)(bh * 128 + tt) * 4 + d16) * 32 + L;
        g_vfh[d] = make_uint4(uh[0], uh[1], uh[2], uh[3]);
        g_vfl[d] = make_uint4(ul[0], ul[1], ul[2], ul[3]);
    }
}

// ---------------- split-bf16 HMMA GEMM core (dense) ----------------
#define GEMM_SMEM_BYTES (2 * 2048 * 16)

#define GEMM_MAIN(AHI, ALO, BHI, BLO, NT16TOT)                                           \
    extern __shared__ uint4 sm4[];                                                        \
    const int tid = threadIdx.x;                                                          \
    const int L = tid & 31, warp = tid >> 5;                                              \
    const int wm = warp >> 2, wn = warp & 3;                                              \
    const int g = L >> 2, i = L & 3;                                                      \
    const int mt0 = blockIdx.y * 8, nt0 = blockIdx.x * 8;                                 \
    float acc[4][4][4];                                                                   \
    _Pragma("unroll")                                                                     \
    for (int a = 0; a < 4; ++a)                                                           \
        _Pragma("unroll")                                                                 \
        for (int b = 0; b < 4; ++b)                                                       \
            _Pragma("unroll")                                                             \
            for (int c = 0; c < 4; ++c) acc[a][b][c] = 0.f;                               \
    _Pragma("unroll")                                                                     \
    for (int c = 0; c < 2; ++c) {                                                         \
        int e = tid + c * 256;                                                            \
        int mt = e >> 6, kt = (e >> 5) & 1, l = e & 31;                                   \
        size_t s = ((size_t)(mt0 + mt) * 64 + kt) * 32 + l;                               \
        cp16(&sm4[(mt * 2 + kt) * 32 + l], &AHI[s]);                                      \
        cp16(&sm4[512 + (mt * 2 + kt) * 32 + l], &ALO[s]);                                \
    }                                                                                     \
    _Pragma("unroll")                                                                     \
    for (int c = 0; c < 2; ++c) {                                                         \
        int e = tid + c * 256;                                                            \
        int kt = e >> 8, nt = (e >> 5) & 7, l = e & 31;                                   \
        size_t s = ((size_t)kt * NT16TOT + nt0 + nt) * 32 + l;                            \
        cp16(&sm4[1024 + (kt * 8 + nt) * 32 + l], &BHI[s]);                               \
        cp16(&sm4[1536 + (kt * 8 + nt) * 32 + l], &BLO[s]);                               \
    }                                                                                     \
    CP_COMMIT(); CP_WAIT0();                                                              \
    __syncthreads();                                                                      \
    for (int st = 0; st < 32; ++st) {                                                     \
        const int cur = st & 1;                                                           \
        const int sb = cur * 2048;                                                        \
        if (st < 31) {                                                                    \
            const int nb = (cur ^ 1) * 2048;                                              \
            const int kg = (st + 1) * 2;                                                  \
            _Pragma("unroll")                                                             \
            for (int c = 0; c < 2; ++c) {                                                 \
                int e = tid + c * 256;                                                    \
                int mt = e >> 6, kt = (e >> 5) & 1, l = e & 31;                           \
                size_t s = ((size_t)(mt0 + mt) * 64 + kg + kt) * 32 + l;                  \
                cp16(&sm4[nb + (mt * 2 + kt) * 32 + l], &AHI[s]);                         \
                cp16(&sm4[nb + 512 + (mt * 2 + kt) * 32 + l], &ALO[s]);                   \
            }                                                                             \
            _Pragma("unroll")                                                             \
            for (int c = 0; c < 2; ++c) {                                                 \
                int e = tid + c * 256;                                                    \
                int kt = e >> 8, nt = (e >> 5) & 7, l = e & 31;                           \
                size_t s = ((size_t)(kg + kt) * NT16TOT + nt0 + nt) * 32 + l;             \
                cp16(&sm4[nb + 1024 + (kt * 8 + nt) * 32 + l], &BHI[s]);                  \
                cp16(&sm4[nb + 1536 + (kt * 8 + nt) * 32 + l], &BLO[s]);                  \
            }                                                                             \
            CP_COMMIT();                                                                  \
        }                                                                                 \
        _Pragma("unroll")                                                                 \
        for (int kt = 0; kt < 2; ++kt) {                                                  \
            uint4 ah[4], al[4], bh[2], bl[2];                                             \
            _Pragma("unroll")                                                             \
            for (int mt = 0; mt < 4; ++mt) {                                              \
                int idx = ((wm * 4 + mt) * 2 + kt) * 32 + L;                              \
                ah[mt] = sm4[sb + idx];                                                   \
                al[mt] = sm4[sb + 512 + idx];                                             \
            }                                                                             \
            _Pragma("unroll")                                                             \
            for (int nt = 0; nt < 2; ++nt) {                                              \
                int idx = (kt * 8 + wn * 2 + nt) * 32 + L;                                \
                bh[nt] = sm4[sb + 1024 + idx];                                            \
                bl[nt] = sm4[sb + 1536 + idx];                                            \
            }                                                                             \
            _Pragma("unroll")                                                             \
            for (int mt = 0; mt < 4; ++mt)                                                \
                _Pragma("unroll")                                                         \
                for (int nt = 0; nt < 2; ++nt) {                                          \
                    float* c0 = acc[mt][nt * 2];                                          \
                    float* c1 = acc[mt][nt * 2 + 1];                                      \
                    mma_bf16(c0, ah[mt], bh[nt].x, bh[nt].y);                             \
                    mma_bf16(c1, ah[mt], bh[nt].z, bh[nt].w);                             \
                    mma_bf16(c0, ah[mt], bl[nt].x, bl[nt].y);                             \
                    mma_bf16(c1, ah[mt], bl[nt].z, bl[nt].w);                             \
                    mma_bf16(c0, al[mt], bh[nt].x, bh[nt].y);                             \
                    mma_bf16(c1, al[mt], bh[nt].z, bh[nt].w);                             \
                }                                                                         \
        }                                                                                 \
        if (st < 31) CP_WAIT0();                                                          \
        __syncthreads();                                                                  \
    }

// ---- QKV GEMM + RoPE epilogue ----
__global__ __launch_bounds__(256)
void qkv_mma_kernel() {
    GEMM_MAIN(g_xhi, g_xlo, g_wqh, g_wql, 192)

    const int n0 = blockIdx.x * 128;
    const int m0 = blockIdx.y * 128;
    const int which = n0 >> 10;
    const int bbb = m0 >> 11;
    const int hh = ((n0 & 1023) >> 6) + (wn >> 1);

#pragma unroll
    for (int mt = 0; mt < 4; ++mt) {
#pragma unroll
        for (int nt = 0; nt < 2; ++nt) {
#pragma unroll
            for (int n8 = 0; n8 < 2; ++n8) {
                const float* c = acc[mt][nt * 2 + n8];
                int d0 = (wn & 1) * 32 + nt * 16 + n8 * 8 + 2 * i;
#pragma unroll
                for (int half = 0; half < 2; ++half) {
                    int t = (m0 & 2047) + wm * 64 + mt * 16 + g + 8 * half;
                    float v0 = c[half * 2], v1 = c[half * 2 + 1];
                    size_t base = (((size_t)(bbb * Hz + hh) * Tz + t) * HDz) + d0;
                    if (which == 2) {
                        *(float2*)&g_v[base] = make_float2(v0, v1);
                    } else {
                        float2 cs = *(const float2*)&g_cos[t * 64 + d0];
                        float2 sn = *(const float2*)&g_sin[t * 64 + d0];
                        float re = v0 * cs.x - v1 * sn.x;
                        float ro = v1 * cs.y + v0 * sn.y;
                        if (which == 0) *(float2*)&g_q[base] = make_float2(re, ro);
                        else            *(float2*)&g_k[base] = make_float2(re, ro);
                    }
                }
            }
        }
    }
}

// ---- Output projection + bias ----
__global__ __launch_bounds__(256)
void proj_mma_kernel(const float* __restrict__ bias, float* __restrict__ out) {
    GEMM_MAIN(g_athi, g_atlo, g_woh, g_wol, 64)

    const int n0 = blockIdx.x * 128;
    const int m0 = blockIdx.y * 128;

#pragma unroll
    for (int mt = 0; mt < 4; ++mt) {
#pragma unroll
        for (int nt = 0; nt < 2; ++nt) {
#pragma unroll
            for (int n8 = 0; n8 < 2; ++n8) {
                const float* c = acc[mt][nt * 2 + n8];
                int col = n0 + wn * 32 + nt * 16 + n8 * 8 + 2 * i;
                float2 bi = *(const float2*)&bias[col];
#pragma unroll
                for (int half = 0; half < 2; ++half) {
                    int m = m0 + wm * 64 + mt * 16 + g + 8 * half;
                    *(float2*)&out[(size_t)m * 1024 + col] =
                        make_float2(c[half * 2] + bi.x, c[half * 2 + 1] + bi.y);
                }
            }
        }
    }
}

// ---------------- HMMA flash attention ----------------
// CTA: 128 q rows x one (b,h); 8 warps x 16q. K-tile 64, 32 iterations.
// smem stage (uint4 units): khi[0,512) klo[512,1024) vhi[1024,1536) vlo[1536,2048)
//   khi layout: [nt4][ds4][32] matching global contiguity; vhi: [tt4][d16 4][32].
#define ATTN_SMEM_BYTES (2 * 2048 * 16)

__global__ __launch_bounds__(256)
void attn_mma_kernel() {
    extern __shared__ uint4 sm4[];
    const int tid = threadIdx.x;
    const int L = tid & 31, w = tid >> 5;
    const int g = L >> 2, i = L & 3;
    const int qb = blockIdx.x;
    const int h = blockIdx.y, bb = blockIdx.z;
    const int bh = bb * Hz + h;
    const int mt = qb * 8 + w;

    // Q fragments (resident): scaled by QSCALE in prep
    uint4 qh[4], ql[4];
#pragma unroll
    for (int ds = 0; ds < 4; ++ds) {
        size_t d = ((size_t)(bh * 128 + mt) * 4 + ds) * 32 + L;
        qh[ds] = g_qfh[d];
        ql[ds] = g_qfl[d];
    }

    float o[8][4];
#pragma unroll
    for (int t = 0; t < 8; ++t)
#pragma unroll
        for (int c = 0; c < 4; ++c) o[t][c] = 0.f;
    float mi_a = -1e30f, mi_b = -1e30f, li_a = 0.f, li_b = 0.f;

    // prologue: stage 0
    {
        size_t base = (size_t)(bh * 128) * 128;   // it = 0
#pragma unroll
        for (int c = 0; c < 8; ++c) {
            int idx = tid + c * 256;
            int r = idx >> 9, off = idx & 511;
            const uint4* src = (r == 0) ? g_kfh + base : (r == 1) ? g_kfl + base
                             : (r == 2) ? g_vfh + base : g_vfl + base;
            cp16(&sm4[r * 512 + off], src + off);
        }
        CP_COMMIT(); CP_WAIT0();
    }
    __syncthreads();

    for (int it = 0; it < 32; ++it) {
        const int cur = it & 1;
        const int sb = cur * 2048;
        if (it < 31) {
            const int nb = (cur ^ 1) * 2048;
            size_t base = (size_t)(bh * 128 + (it + 1) * 4) * 128;
#pragma unroll
            for (int c = 0; c < 8; ++c) {
                int idx = tid + c * 256;
                int r = idx >> 9, off = idx & 511;
                const uint4* src = (r == 0) ? g_kfh + base : (r == 1) ? g_kfl + base
                                 : (r == 2) ? g_vfh + base : g_vfl + base;
                cp16(&sm4[nb + r * 512 + off], src + off);
            }
            CP_COMMIT();
        }

        // ---- GEMM1: S(16q x 64k, log2 domain) = Q . K^T ----
        float s[8][4];
#pragma unroll
        for (int t = 0; t < 8; ++t)
#pragma unroll
            for (int c = 0; c < 4; ++c) s[t][c] = 0.f;

#pragma unroll
        for (int ds = 0; ds < 4; ++ds) {
            uint4 kh[4], kl[4];
#pragma unroll
            for (int nt = 0; nt < 4; ++nt) {
                int idx = (nt * 4 + ds) * 32 + L;
                kh[nt] = sm4[sb + idx];
                kl[nt] = sm4[sb + 512 + idx];
            }
#pragma unroll
            for (int nt = 0; nt < 4; ++nt) {
                mma_bf16(s[2*nt],   qh[ds], kh[nt].x, kh[nt].y);
                mma_bf16(s[2*nt+1], qh[ds], kh[nt].z, kh[nt].w);
                mma_bf16(s[2*nt],   qh[ds], kl[nt].x, kl[nt].y);
                mma_bf16(s[2*nt+1], qh[ds], kl[nt].z, kl[nt].w);
                mma_bf16(s[2*nt],   ql[ds], kh[nt].x, kh[nt].y);
                mma_bf16(s[2*nt+1], ql[ds], kh[nt].z, kh[nt].w);
            }
        }

        // ---- online softmax (base-2): rows g (c0,c1) and g+8 (c2,c3) ----
        float mxa = -1e30f, mxb = -1e30f;
#pragma unroll
        for (int t = 0; t < 8; ++t) {
            mxa = fmaxf(mxa, fmaxf(s[t][0], s[t][1]));
            mxb = fmaxf(mxb, fmaxf(s[t][2], s[t][3]));
        }
        mxa = fmaxf(mxa, __shfl_xor_sync(0xffffffffu, mxa, 1));
        mxa = fmaxf(mxa, __shfl_xor_sync(0xffffffffu, mxa, 2));
        mxb = fmaxf(mxb, __shfl_xor_sync(0xffffffffu, mxb, 1));
        mxb = fmaxf(mxb, __shfl_xor_sync(0xffffffffu, mxb, 2));
        float mna = fmaxf(mi_a, mxa), mnb = fmaxf(mi_b, mxb);
        float fa = exp2p(mi_a - mna), fb = exp2p(mi_b - mnb);
        mi_a = mna; mi_b = mnb;

        float suma = 0.f, sumb = 0.f;
#pragma unroll
        for (int t = 0; t < 8; ++t) {
            float p0 = exp2p(s[t][0] - mna);
            float p1 = exp2p(s[t][1] - mna);
            float p2 = exp2p(s[t][2] - mnb);
            float p3 = exp2p(s[t][3] - mnb);
            s[t][0] = p0; s[t][1] = p1; s[t][2] = p2; s[t][3] = p3;
            suma += p0 + p1; sumb += p2 + p3;
        }
        suma += __shfl_xor_sync(0xffffffffu, suma, 1);
        suma += __shfl_xor_sync(0xffffffffu, suma, 2);
        sumb += __shfl_xor_sync(0xffffffffu, sumb, 1);
        sumb += __shfl_xor_sync(0xffffffffu, sumb, 2);
        li_a = li_a * fa + suma;
        li_b = li_b * fb + sumb;

#pragma unroll
        for (int t = 0; t < 8; ++t) {
            o[t][0] *= fa; o[t][1] *= fa;
            o[t][2] *= fb; o[t][3] *= fb;
        }

        // ---- GEMM2: O += P . V  (P register-resident, split hi/lo) ----
#pragma unroll
        for (int sk = 0; sk < 4; ++sk) {
            // pack P A-fragment for kstep sk from C tiles 2sk, 2sk+1
            uint4 ph, pl;
            ph.x = pkbf(s[2*sk][0],   s[2*sk][1]);
            ph.y = pkbf(s[2*sk][2],   s[2*sk][3]);
            ph.z = pkbf(s[2*sk+1][0], s[2*sk+1][1]);
            ph.w = pkbf(s[2*sk+1][2], s[2*sk+1][3]);
            {
                float h0 = __uint_as_float(ph.x << 16), h1 = __uint_as_float(ph.x & 0xffff0000u);
                pl.x = pkbf(s[2*sk][0] - h0, s[2*sk][1] - h1);
                h0 = __uint_as_float(ph.y << 16); h1 = __uint_as_float(ph.y & 0xffff0000u);
                pl.y = pkbf(s[2*sk][2] - h0, s[2*sk][3] - h1);
                h0 = __uint_as_float(ph.z << 16); h1 = __uint_as_float(ph.z & 0xffff0000u);
                pl.z = pkbf(s[2*sk+1][0] - h0, s[2*sk+1][1] - h1);
                h0 = __uint_as_float(ph.w << 16); h1 = __uint_as_float(ph.w & 0xffff0000u);
                pl.w = pkbf(s[2*sk+1][2] - h0, s[2*sk+1][3] - h1);
            }
#pragma unroll
            for (int d16 = 0; d16 < 4; ++d16) {
                int idx = (sk * 4 + d16) * 32 + L;
                uint4 vh = sm4[sb + 1024 + idx];
                uint4 vl = sm4[sb + 1536 + idx];
                mma_bf16(o[2*d16],   ph, vh.x, vh.y);
                mma_bf16(o[2*d16+1], ph, vh.z, vh.w);
                mma_bf16(o[2*d16],   ph, vl.x, vl.y);
                mma_bf16(o[2*d16+1], ph, vl.z, vl.w);
                mma_bf16(o[2*d16],   pl, vh.x, vh.y);
                mma_bf16(o[2*d16+1], pl, vh.z, vh.w);
            }
        }

        if (it < 31) CP_WAIT0();
        __syncthreads();
    }

    // ---- epilogue: normalize, write g_att[b*T + t][h*64 + d] ----
    float inva = 1.f / li_a, invb = 1.f / li_b;
    int row_a = qb * 128 + w * 16 + g;
    int row_b = row_a + 8;
#pragma unroll
    for (int t = 0; t < 8; ++t) {
        int col = h * 64 + t * 8 + 2 * i;
        *(float2*)&g_att[((size_t)(bb * Tz + row_a)) * DIMz + col] =
            make_float2(o[t][0] * inva, o[t][1] * inva);
        *(float2*)&g_att[((size_t)(bb * Tz + row_b)) * DIMz + col] =
            make_float2(o[t][2] * invb, o[t][3] * invb);
    }
}

// ---------------- launch ----------------
extern "C" void kernel_launch(void* const* d_in, const int* in_sizes, int n_in,
                              void* d_out, int out_size) {
    (void)in_sizes; (void)n_in; (void)out_size;
    const float* x    = (const float*)d_in[0];
    const float* Wqkv = (const float*)d_in[1];
    const float* Wout = (const float*)d_in[2];
    const float* bout = (const float*)d_in[3];
    float* out = (float*)d_out;

    cudaFuncSetAttribute(qkv_mma_kernel, cudaFuncAttributeMaxDynamicSharedMemorySize,
                         GEMM_SMEM_BYTES);
    cudaFuncSetAttribute(proj_mma_kernel, cudaFuncAttributeMaxDynamicSharedMemorySize,
                         GEMM_SMEM_BYTES);
    cudaFuncSetAttribute(attn_mma_kernel, cudaFuncAttributeMaxDynamicSharedMemorySize,
                         ATTN_SMEM_BYTES);

    rope_tables_kernel<<<(Tz * HDz) / 256, 256>>>();
    prep_x_kernel <<<(Mz/16)*(DIMz/16)*32/256, 256>>>(x);
    prep_wq_kernel<<<(DIMz/16)*(N3z/16)*32/256, 256>>>(Wqkv);
    prep_wo_kernel<<<(DIMz/16)*(DIMz/16)*32/256, 256>>>(Wout);

    qkv_mma_kernel<<<dim3(N3z / 128, Mz / 128), 256, GEMM_SMEM_BYTES>>>();

    prep_qf_kernel<<<512, 256>>>();
    prep_kf_kernel<<<512, 256>>>();
    prep_vf_kernel<<<512, 256>>>();

    attn_mma_kernel<<<dim3(Tz / 128, Hz, Bz), 256, ATTN_SMEM_BYTES>>>();

    prep_att_kernel<<<(Mz/16)*(DIMz/16)*32/256, 256>>>();
    proj_mma_kernel<<<dim3(DIMz / 128, Mz / 128), 256, GEMM_SMEM_BYTES>>>(bout, out);
}

// round 10
// speedup vs baseline: 2.7317x; 1.1204x over previous
#include <cuda_runtime.h>
#include <cuda_bf16.h>

#define Bz   2
#define Tz   2048
#define DIMz 1024
#define Hz   16
#define HDz  64
#define Mz   (Bz*Tz)      /* 4096 */
#define N3z  (3*DIMz)     /* 3072 */

// scale folded into Q fragments: (1/8) * log2(e)
#define QSCALE 0.18033688011112042f

// ---------------- scratch (device globals: allocation-free) ----------------
__device__ float g_v  [Bz*Hz*Tz*HDz];   // [bh][t][d]
__device__ float g_att[Mz*DIMz];        // [b*t][dim]
__device__ float g_cos[Tz*HDz];
__device__ float g_sin[Tz*HDz];

// fragment-order bf16 hi/lo operands (16B chunks) for dense GEMMs
__device__ uint4 g_xhi [ (Mz/16)*(DIMz/16)*32 ];
__device__ uint4 g_xlo [ (Mz/16)*(DIMz/16)*32 ];
__device__ uint4 g_wqh [ (DIMz/16)*(N3z/16)*32 ];
__device__ uint4 g_wql [ (DIMz/16)*(N3z/16)*32 ];
__device__ uint4 g_woh [ (DIMz/16)*(DIMz/16)*32 ];
__device__ uint4 g_wol [ (DIMz/16)*(DIMz/16)*32 ];
__device__ uint4 g_athi[ (Mz/16)*(DIMz/16)*32 ];
__device__ uint4 g_atlo[ (Mz/16)*(DIMz/16)*32 ];

// attention fragment arrays: per bh, 128 16-tiles x 4 16-steps x 32 lanes
#define BH_FRAG (128*4*32)
__device__ uint4 g_qfh[32*BH_FRAG];   // Q A-frags, scaled by QSCALE
__device__ uint4 g_qfl[32*BH_FRAG];
__device__ uint4 g_kfh[32*BH_FRAG];   // K B-frags
__device__ uint4 g_kfl[32*BH_FRAG];
__device__ uint4 g_vfh[32*BH_FRAG];   // V B-frags
__device__ uint4 g_vfl[32*BH_FRAG];

// ---------------- helpers ----------------
__device__ __forceinline__ void cp16(void* dst, const void* src) {
    unsigned d = (unsigned)__cvta_generic_to_shared(dst);
    asm volatile("cp.async.cg.shared.global [%0], [%1], 16;" :: "r"(d), "l"(src));
}
#define CP_COMMIT() asm volatile("cp.async.commit_group;")
#define CP_WAIT0()  asm volatile("cp.async.wait_group 0;")

__device__ __forceinline__ void mma_bf16(float* c, const uint4& a, unsigned b0, unsigned b1) {
    asm("mma.sync.aligned.m16n8k16.row.col.f32.bf16.bf16.f32 "
        "{%0,%1,%2,%3}, {%4,%5,%6,%7}, {%8,%9}, {%0,%1,%2,%3};"
        : "+f"(c[0]), "+f"(c[1]), "+f"(c[2]), "+f"(c[3])
        : "r"(a.x), "r"(a.y), "r"(a.z), "r"(a.w), "r"(b0), "r"(b1));
}

__device__ __forceinline__ unsigned pkbf(float x, float y) {
    __nv_bfloat162 h = __floats2bfloat162_rn(x, y);
    return *reinterpret_cast<unsigned*>(&h);
}
__device__ __forceinline__ void split2(float a, float b, unsigned &h, unsigned &l) {
    h = pkbf(a, b);
    float ha = __uint_as_float(h << 16);
    float hb = __uint_as_float(h & 0xffff0000u);
    l = pkbf(a - ha, b - hb);
}

// fast 2^z for z <= 0 on FMA/ALU pipes
__device__ __forceinline__ float exp2p(float z) {
    z = fmaxf(z, -120.f);
    float fn = rintf(z);
    float r = z - fn;
    int n = (int)fn;
    float p = 0.0013333558146428443f;
    p = fmaf(p, r, 0.009618129107628477f);
    p = fmaf(p, r, 0.05550410866482158f);
    p = fmaf(p, r, 0.24022650695910072f);
    p = fmaf(p, r, 0.6931471805599453f);
    p = fmaf(p, r, 1.0f);
    return __int_as_float(__float_as_int(p) + (n << 23));
}

// ---------------- RoPE cos/sin tables ----------------
__global__ void rope_tables_kernel() {
    int idx = blockIdx.x * 256 + threadIdx.x;
    int t = idx >> 6, d = idx & 63;
    float inv = expf(-(float)(d & 31) * (9.210340371976184f / 32.0f));
    float ang = (float)t * inv;
    g_cos[idx] = cosf(ang);
    g_sin[idx] = sinf(ang);
}

// ---------------- prep: fp32 -> frag-order bf16 hi/lo (dense GEMMs) ----------------
__device__ __forceinline__ void prepA_body(const float* __restrict__ src,
                                           uint4* __restrict__ dhi, uint4* __restrict__ dlo,
                                           int Kt, int gid) {
    int L = gid & 31, at = gid >> 5;
    int mt = at / Kt, kt = at - mt * Kt;
    int g = L >> 2, i = L & 3;
    const int K = Kt * 16;
    unsigned uh[4], ul[4];
#pragma unroll
    for (int s = 0; s < 4; ++s) {
        int row = mt * 16 + g + 8 * (s & 1);
        int k   = kt * 16 + 2 * i + 8 * (s >> 1);
        float2 f = *(const float2*)(src + (size_t)row * K + k);
        split2(f.x, f.y, uh[s], ul[s]);
    }
    size_t d = (size_t)at * 32 + L;
    dhi[d] = make_uint4(uh[0], uh[1], uh[2], uh[3]);
    dlo[d] = make_uint4(ul[0], ul[1], ul[2], ul[3]);
}

__device__ __forceinline__ void prepB_body(const float* __restrict__ src,
                                           uint4* __restrict__ dhi, uint4* __restrict__ dlo,
                                           int Nt, int N, int gid) {
    int L = gid & 31, bt = gid >> 5;
    int kt = bt / Nt, nt = bt - kt * Nt;
    int g = L >> 2, i = L & 3;
    unsigned uh[4], ul[4];
#pragma unroll
    for (int s = 0; s < 4; ++s) {
        int k   = kt * 16 + 2 * i + 8 * (s & 1);
        int col = nt * 16 + g + 8 * (s >> 1);
        float f0 = src[(size_t)k * N + col];
        float f1 = src[(size_t)(k + 1) * N + col];
        split2(f0, f1, uh[s], ul[s]);
    }
    size_t d = (size_t)bt * 32 + L;
    dhi[d] = make_uint4(uh[0], uh[1], uh[2], uh[3]);
    dlo[d] = make_uint4(ul[0], ul[1], ul[2], ul[3]);
}

__global__ void prep_x_kernel(const float* __restrict__ src) {
    prepA_body(src, g_xhi, g_xlo, DIMz / 16, blockIdx.x * 256 + threadIdx.x);
}
__global__ void prep_att_kernel() {
    prepA_body(g_att, g_athi, g_atlo, DIMz / 16, blockIdx.x * 256 + threadIdx.x);
}
__global__ void prep_wq_kernel(const float* __restrict__ src) {
    prepB_body(src, g_wqh, g_wql, N3z / 16, N3z, blockIdx.x * 256 + threadIdx.x);
}
__global__ void prep_wo_kernel(const float* __restrict__ src) {
    prepB_body(src, g_woh, g_wol, DIMz / 16, DIMz, blockIdx.x * 256 + threadIdx.x);
}

// ---------------- prep: V fp32 -> B-frag order hi/lo ----------------
__global__ void prep_vf_kernel() {
    int gid = blockIdx.x * 256 + threadIdx.x;
    int L = gid & 31, rest = gid >> 5;
    int tt = rest & 127, bh = rest >> 7;
    int g = L >> 2, i = L & 3;
    const float* src = g_v + (size_t)bh * Tz * HDz;
#pragma unroll
    for (int d16 = 0; d16 < 4; ++d16) {
        unsigned uh[4], ul[4];
#pragma unroll
        for (int s = 0; s < 4; ++s) {
            int k   = tt * 16 + 2 * i + 8 * (s & 1);      // t (contraction)
            int col = d16 * 16 + g + 8 * (s >> 1);        // d
            float f0 = src[(size_t)k * 64 + col];
            float f1 = src[(size_t)(k + 1) * 64 + col];
            split2(f0, f1, uh[s], ul[s]);
        }
        size_t d = ((size_t)(bh * 128 + tt) * 4 + d16) * 32 + L;
        g_vfh[d] = make_uint4(uh[0], uh[1], uh[2], uh[3]);
        g_vfl[d] = make_uint4(ul[0], ul[1], ul[2], ul[3]);
    }
}

// ---------------- split-bf16 HMMA GEMM core (pass-major MMA ordering) ----------------
#define GEMM_SMEM_BYTES (2 * 2048 * 16)

#define GEMM_MAIN(AHI, ALO, BHI, BLO, NT16TOT)                                           \
    extern __shared__ uint4 sm4[];                                                        \
    const int tid = threadIdx.x;                                                          \
    const int L = tid & 31, warp = tid >> 5;                                              \
    const int wm = warp >> 2, wn = warp & 3;                                              \
    const int g = L >> 2, i = L & 3;                                                      \
    const int mt0 = blockIdx.y * 8, nt0 = blockIdx.x * 8;                                 \
    float acc[4][4][4];                                                                   \
    _Pragma("unroll")                                                                     \
    for (int a = 0; a < 4; ++a)                                                           \
        _Pragma("unroll")                                                                 \
        for (int b = 0; b < 4; ++b)                                                       \
            _Pragma("unroll")                                                             \
            for (int c = 0; c < 4; ++c) acc[a][b][c] = 0.f;                               \
    _Pragma("unroll")                                                                     \
    for (int c = 0; c < 2; ++c) {                                                         \
        int e = tid + c * 256;                                                            \
        int mt = e >> 6, kt = (e >> 5) & 1, l = e & 31;                                   \
        size_t s = ((size_t)(mt0 + mt) * 64 + kt) * 32 + l;                               \
        cp16(&sm4[(mt * 2 + kt) * 32 + l], &AHI[s]);                                      \
        cp16(&sm4[512 + (mt * 2 + kt) * 32 + l], &ALO[s]);                                \
    }                                                                                     \
    _Pragma("unroll")                                                                     \
    for (int c = 0; c < 2; ++c) {                                                         \
        int e = tid + c * 256;                                                            \
        int kt = e >> 8, nt = (e >> 5) & 7, l = e & 31;                                   \
        size_t s = ((size_t)kt * NT16TOT + nt0 + nt) * 32 + l;                            \
        cp16(&sm4[1024 + (kt * 8 + nt) * 32 + l], &BHI[s]);                               \
        cp16(&sm4[1536 + (kt * 8 + nt) * 32 + l], &BLO[s]);                               \
    }                                                                                     \
    CP_COMMIT(); CP_WAIT0();                                                              \
    __syncthreads();                                                                      \
    for (int st = 0; st < 32; ++st) {                                                     \
        const int cur = st & 1;                                                           \
        const int sb = cur * 2048;                                                        \
        if (st < 31) {                                                                    \
            const int nb = (cur ^ 1) * 2048;                                              \
            const int kg = (st + 1) * 2;                                                  \
            _Pragma("unroll")                                                             \
            for (int c = 0; c < 2; ++c) {                                                 \
                int e = tid + c * 256;                                                    \
                int mt = e >> 6, kt = (e >> 5) & 1, l = e & 31;                           \
                size_t s = ((size_t)(mt0 + mt) * 64 + kg + kt) * 32 + l;                  \
                cp16(&sm4[nb + (mt * 2 + kt) * 32 + l], &AHI[s]);                         \
                cp16(&sm4[nb + 512 + (mt * 2 + kt) * 32 + l], &ALO[s]);                   \
            }                                                                             \
            _Pragma("unroll")                                                             \
            for (int c = 0; c < 2; ++c) {                                                 \
                int e = tid + c * 256;                                                    \
                int kt = e >> 8, nt = (e >> 5) & 7, l = e & 31;                           \
                size_t s = ((size_t)(kg + kt) * NT16TOT + nt0 + nt) * 32 + l;             \
                cp16(&sm4[nb + 1024 + (kt * 8 + nt) * 32 + l], &BHI[s]);                  \
                cp16(&sm4[nb + 1536 + (kt * 8 + nt) * 32 + l], &BLO[s]);                  \
            }                                                                             \
            CP_COMMIT();                                                                  \
        }                                                                                 \
        _Pragma("unroll")                                                                 \
        for (int kt = 0; kt < 2; ++kt) {                                                  \
            uint4 ah[4], al[4], bh[2], bl[2];                                             \
            _Pragma("unroll")                                                             \
            for (int mt = 0; mt < 4; ++mt) {                                              \
                int idx = ((wm * 4 + mt) * 2 + kt) * 32 + L;                              \
                ah[mt] = sm4[sb + idx];                                                   \
                al[mt] = sm4[sb + 512 + idx];                                             \
            }                                                                             \
            _Pragma("unroll")                                                             \
            for (int nt = 0; nt < 2; ++nt) {                                              \
                int idx = (kt * 8 + wn * 2 + nt) * 32 + L;                                \
                bh[nt] = sm4[sb + 1024 + idx];                                            \
                bl[nt] = sm4[sb + 1536 + idx];                                            \
            }                                                                             \
            /* pass 1: ah x bh */                                                         \
            _Pragma("unroll")                                                             \
            for (int mt = 0; mt < 4; ++mt)                                                \
                _Pragma("unroll")                                                         \
                for (int nt = 0; nt < 2; ++nt) {                                          \
                    mma_bf16(acc[mt][nt * 2],     ah[mt], bh[nt].x, bh[nt].y);            \
                    mma_bf16(acc[mt][nt * 2 + 1], ah[mt], bh[nt].z, bh[nt].w);            \
                }                                                                         \
            /* pass 2: ah x bl */                                                         \
            _Pragma("unroll")                                                             \
            for (int mt = 0; mt < 4; ++mt)                                                \
                _Pragma("unroll")                                                         \
                for (int nt = 0; nt < 2; ++nt) {                                          \
                    mma_bf16(acc[mt][nt * 2],     ah[mt], bl[nt].x, bl[nt].y);            \
                    mma_bf16(acc[mt][nt * 2 + 1], ah[mt], bl[nt].z, bl[nt].w);            \
                }                                                                         \
            /* pass 3: al x bh */                                                         \
            _Pragma("unroll")                                                             \
            for (int mt = 0; mt < 4; ++mt)                                                \
                _Pragma("unroll")                                                         \
                for (int nt = 0; nt < 2; ++nt) {                                          \
                    mma_bf16(acc[mt][nt * 2],     al[mt], bh[nt].x, bh[nt].y);            \
                    mma_bf16(acc[mt][nt * 2 + 1], al[mt], bh[nt].z, bh[nt].w);            \
                }                                                                         \
        }                                                                                 \
        if (st < 31) CP_WAIT0();                                                          \
        __syncthreads();                                                                  \
    }

// ---- QKV GEMM + fused RoPE + direct Q/K-fragment epilogue ----
__global__ __launch_bounds__(256)
void qkv_mma_kernel() {
    GEMM_MAIN(g_xhi, g_xlo, g_wqh, g_wql, 192)

    const int n0 = blockIdx.x * 128;
    const int m0 = blockIdx.y * 128;
    const int which = n0 >> 10;
    const int bbat = m0 >> 11;
    const int hh = ((n0 & 1023) >> 6) + (wn >> 1);
    const int bh = bbat * Hz + hh;

#pragma unroll
    for (int mt = 0; mt < 4; ++mt) {
#pragma unroll
        for (int nt = 0; nt < 2; ++nt) {
            unsigned fh[4], fl[4];
#pragma unroll
            for (int n8 = 0; n8 < 2; ++n8) {
                const float* c = acc[mt][nt * 2 + n8];
                int d0 = (wn & 1) * 32 + nt * 16 + n8 * 8 + 2 * i;
#pragma unroll
                for (int half = 0; half < 2; ++half) {
                    int t = (m0 & 2047) + wm * 64 + mt * 16 + g + 8 * half;
                    float v0 = c[half * 2], v1 = c[half * 2 + 1];
                    if (which == 2) {
                        *(float2*)&g_v[(((size_t)bh * Tz + t) * HDz) + d0] =
                            make_float2(v0, v1);
                    } else {
                        float2 cs = *(const float2*)&g_cos[t * 64 + d0];
                        float2 sn = *(const float2*)&g_sin[t * 64 + d0];
                        float re = v0 * cs.x - v1 * sn.x;
                        float ro = v1 * cs.y + v0 * sn.y;
                        if (which == 0) { re *= QSCALE; ro *= QSCALE; }
                        // Q A-frag word: s = half + 2*n8 ; K B-frag word: s = n8 + 2*half
                        int s = (which == 0) ? (half + 2 * n8) : (n8 + 2 * half);
                        split2(re, ro, fh[s], fl[s]);
                    }
                }
            }
            if (which < 2) {
                int mtq = ((m0 & 2047) >> 4) + wm * 4 + mt;   // 16-row tile of t
                int ds = (wn & 1) * 2 + nt;                    // 16-col tile of d
                size_t idx = ((size_t)(bh * 128 + mtq) * 4 + ds) * 32 + L;
                uint4 vh = make_uint4(fh[0], fh[1], fh[2], fh[3]);
                uint4 vl = make_uint4(fl[0], fl[1], fl[2], fl[3]);
                if (which == 0) { g_qfh[idx] = vh; g_qfl[idx] = vl; }
                else            { g_kfh[idx] = vh; g_kfl[idx] = vl; }
            }
        }
    }
}

// ---- Output projection + bias ----
__global__ __launch_bounds__(256)
void proj_mma_kernel(const float* __restrict__ bias, float* __restrict__ out) {
    GEMM_MAIN(g_athi, g_atlo, g_woh, g_wol, 64)

    const int n0 = blockIdx.x * 128;
    const int m0 = blockIdx.y * 128;

#pragma unroll
    for (int mt = 0; mt < 4; ++mt) {
#pragma unroll
        for (int nt = 0; nt < 2; ++nt) {
#pragma unroll
            for (int n8 = 0; n8 < 2; ++n8) {
                const float* c = acc[mt][nt * 2 + n8];
                int col = n0 + wn * 32 + nt * 16 + n8 * 8 + 2 * i;
                float2 bi = *(const float2*)&bias[col];
#pragma unroll
                for (int half = 0; half < 2; ++half) {
                    int m = m0 + wm * 64 + mt * 16 + g + 8 * half;
                    *(float2*)&out[(size_t)m * 1024 + col] =
                        make_float2(c[half * 2] + bi.x, c[half * 2 + 1] + bi.y);
                }
            }
        }
    }
}

// ---------------- HMMA flash attention (pass-major MMAs, occupancy 2) ----------------
#define ATTN_SMEM_BYTES (2 * 2048 * 16)

__global__ __launch_bounds__(256, 2)
void attn_mma_kernel() {
    extern __shared__ uint4 asm4[];
    const int tid = threadIdx.x;
    const int L = tid & 31, w = tid >> 5;
    const int g = L >> 2, i = L & 3;
    const int qb = blockIdx.x;
    const int h = blockIdx.y, bb = blockIdx.z;
    const int bh = bb * Hz + h;
    const int mt = qb * 8 + w;

    const uint4* qfh = g_qfh + ((size_t)(bh * 128 + mt) * 4) * 32 + L;
    const uint4* qfl = g_qfl + ((size_t)(bh * 128 + mt) * 4) * 32 + L;

    float o[8][4];
#pragma unroll
    for (int t = 0; t < 8; ++t)
#pragma unroll
        for (int c = 0; c < 4; ++c) o[t][c] = 0.f;
    float mi_a = -1e30f, mi_b = -1e30f, li_a = 0.f, li_b = 0.f;

    {
        size_t base = (size_t)(bh * 128) * 128;
#pragma unroll
        for (int c = 0; c < 8; ++c) {
            int idx = tid + c * 256;
            int r = idx >> 9, off = idx & 511;
            const uint4* src = (r == 0) ? g_kfh + base : (r == 1) ? g_kfl + base
                             : (r == 2) ? g_vfh + base : g_vfl + base;
            cp16(&asm4[r * 512 + off], src + off);
        }
        CP_COMMIT(); CP_WAIT0();
    }
    __syncthreads();

    for (int it = 0; it < 32; ++it) {
        const int cur = it & 1;
        const int sb = cur * 2048;
        if (it < 31) {
            const int nbuf = (cur ^ 1) * 2048;
            size_t base = (size_t)(bh * 128 + (it + 1) * 4) * 128;
#pragma unroll
            for (int c = 0; c < 8; ++c) {
                int idx = tid + c * 256;
                int r = idx >> 9, off = idx & 511;
                const uint4* src = (r == 0) ? g_kfh + base : (r == 1) ? g_kfl + base
                                 : (r == 2) ? g_vfh + base : g_vfl + base;
                cp16(&asm4[nbuf + r * 512 + off], src + off);
            }
            CP_COMMIT();
        }

        // ---- GEMM1: S = Q.K^T (log2 domain), pass-major ----
        float s[8][4];
#pragma unroll
        for (int t = 0; t < 8; ++t)
#pragma unroll
            for (int c = 0; c < 4; ++c) s[t][c] = 0.f;

#pragma unroll
        for (int ds = 0; ds < 4; ++ds) {
            uint4 qh = qfh[ds * 32];
            uint4 ql = qfl[ds * 32];
            uint4 kh[4], kl[4];
#pragma unroll
            for (int nt = 0; nt < 4; ++nt) {
                int idx = (nt * 4 + ds) * 32 + L;
                kh[nt] = asm4[sb + idx];
                kl[nt] = asm4[sb + 512 + idx];
            }
#pragma unroll
            for (int nt = 0; nt < 4; ++nt) {
                mma_bf16(s[2*nt],   qh, kh[nt].x, kh[nt].y);
                mma_bf16(s[2*nt+1], qh, kh[nt].z, kh[nt].w);
            }
#pragma unroll
            for (int nt = 0; nt < 4; ++nt) {
                mma_bf16(s[2*nt],   qh, kl[nt].x, kl[nt].y);
                mma_bf16(s[2*nt+1], qh, kl[nt].z, kl[nt].w);
            }
#pragma unroll
            for (int nt = 0; nt < 4; ++nt) {
                mma_bf16(s[2*nt],   ql, kh[nt].x, kh[nt].y);
                mma_bf16(s[2*nt+1], ql, kh[nt].z, kh[nt].w);
            }
        }

        // ---- online softmax (base-2) ----
        float mxa = -1e30f, mxb = -1e30f;
#pragma unroll
        for (int t = 0; t < 8; ++t) {
            mxa = fmaxf(mxa, fmaxf(s[t][0], s[t][1]));
            mxb = fmaxf(mxb, fmaxf(s[t][2], s[t][3]));
        }
        mxa = fmaxf(mxa, __shfl_xor_sync(0xffffffffu, mxa, 1));
        mxa = fmaxf(mxa, __shfl_xor_sync(0xffffffffu, mxa, 2));
        mxb = fmaxf(mxb, __shfl_xor_sync(0xffffffffu, mxb, 1));
        mxb = fmaxf(mxb, __shfl_xor_sync(0xffffffffu, mxb, 2));
        float mna = fmaxf(mi_a, mxa), mnb = fmaxf(mi_b, mxb);
        float fa = exp2p(mi_a - mna), fb = exp2p(mi_b - mnb);
        mi_a = mna; mi_b = mnb;

        float suma = 0.f, sumb = 0.f;
#pragma unroll
        for (int t = 0; t < 8; ++t) {
            float p0 = exp2p(s[t][0] - mna);
            float p1 = exp2p(s[t][1] - mna);
            float p2 = exp2p(s[t][2] - mnb);
            float p3 = exp2p(s[t][3] - mnb);
            s[t][0] = p0; s[t][1] = p1; s[t][2] = p2; s[t][3] = p3;
            suma += p0 + p1; sumb += p2 + p3;
        }
        suma += __shfl_xor_sync(0xffffffffu, suma, 1);
        suma += __shfl_xor_sync(0xffffffffu, suma, 2);
        sumb += __shfl_xor_sync(0xffffffffu, sumb, 1);
        sumb += __shfl_xor_sync(0xffffffffu, sumb, 2);
        li_a = li_a * fa + suma;
        li_b = li_b * fb + sumb;

#pragma unroll
        for (int t = 0; t < 8; ++t) {
            o[t][0] *= fa; o[t][1] *= fa;
            o[t][2] *= fb; o[t][3] *= fb;
        }

        // ---- GEMM2: O += P.V, pass-major per k-step ----
#pragma unroll
        for (int sk = 0; sk < 4; ++sk) {
            uint4 ph, pl;
            ph.x = pkbf(s[2*sk][0],   s[2*sk][1]);
            ph.y = pkbf(s[2*sk][2],   s[2*sk][3]);
            ph.z = pkbf(s[2*sk+1][0], s[2*sk+1][1]);
            ph.w = pkbf(s[2*sk+1][2], s[2*sk+1][3]);
            {
                float h0 = __uint_as_float(ph.x << 16), h1 = __uint_as_float(ph.x & 0xffff0000u);
                pl.x = pkbf(s[2*sk][0] - h0, s[2*sk][1] - h1);
                h0 = __uint_as_float(ph.y << 16); h1 = __uint_as_float(ph.y & 0xffff0000u);
                pl.y = pkbf(s[2*sk][2] - h0, s[2*sk][3] - h1);
                h0 = __uint_as_float(ph.z << 16); h1 = __uint_as_float(ph.z & 0xffff0000u);
                pl.z = pkbf(s[2*sk+1][0] - h0, s[2*sk+1][1] - h1);
                h0 = __uint_as_float(ph.w << 16); h1 = __uint_as_float(ph.w & 0xffff0000u);
                pl.w = pkbf(s[2*sk+1][2] - h0, s[2*sk+1][3] - h1);
            }
            uint4 vh[4], vl[4];
#pragma unroll
            for (int d16 = 0; d16 < 4; ++d16) {
                int idx = (sk * 4 + d16) * 32 + L;
                vh[d16] = asm4[sb + 1024 + idx];
                vl[d16] = asm4[sb + 1536 + idx];
            }
#pragma unroll
            for (int d16 = 0; d16 < 4; ++d16) {
                mma_bf16(o[2*d16],   ph, vh[d16].x, vh[d16].y);
                mma_bf16(o[2*d16+1], ph, vh[d16].z, vh[d16].w);
            }
#pragma unroll
            for (int d16 = 0; d16 < 4; ++d16) {
                mma_bf16(o[2*d16],   ph, vl[d16].x, vl[d16].y);
                mma_bf16(o[2*d16+1], ph, vl[d16].z, vl[d16].w);
            }
#pragma unroll
            for (int d16 = 0; d16 < 4; ++d16) {
                mma_bf16(o[2*d16],   pl, vh[d16].x, vh[d16].y);
                mma_bf16(o[2*d16+1], pl, vh[d16].z, vh[d16].w);
            }
        }

        if (it < 31) CP_WAIT0();
        __syncthreads();
    }

    // ---- epilogue: normalize, write g_att[b*T + t][h*64 + d] ----
    float inva = 1.f / li_a, invb = 1.f / li_b;
    int row_a = qb * 128 + w * 16 + g;
    int row_b = row_a + 8;
#pragma unroll
    for (int t = 0; t < 8; ++t) {
        int col = h * 64 + t * 8 + 2 * i;
        *(float2*)&g_att[((size_t)(bb * Tz + row_a)) * DIMz + col] =
            make_float2(o[t][0] * inva, o[t][1] * inva);
        *(float2*)&g_att[((size_t)(bb * Tz + row_b)) * DIMz + col] =
            make_float2(o[t][2] * invb, o[t][3] * invb);
    }
}

// ---------------- launch ----------------
extern "C" void kernel_launch(void* const* d_in, const int* in_sizes, int n_in,
                              void* d_out, int out_size) {
    (void)in_sizes; (void)n_in; (void)out_size;
    const float* x    = (const float*)d_in[0];
    const float* Wqkv = (const float*)d_in[1];
    const float* Wout = (const float*)d_in[2];
    const float* bout = (const float*)d_in[3];
    float* out = (float*)d_out;

    cudaFuncSetAttribute(qkv_mma_kernel, cudaFuncAttributeMaxDynamicSharedMemorySize,
                         GEMM_SMEM_BYTES);
    cudaFuncSetAttribute(proj_mma_kernel, cudaFuncAttributeMaxDynamicSharedMemorySize,
                         GEMM_SMEM_BYTES);
    cudaFuncSetAttribute(attn_mma_kernel, cudaFuncAttributeMaxDynamicSharedMemorySize,
                         ATTN_SMEM_BYTES);

    rope_tables_kernel<<<(Tz * HDz) / 256, 256>>>();
    prep_x_kernel <<<(Mz/16)*(DIMz/16)*32/256, 256>>>(x);
    prep_wq_kernel<<<(DIMz/16)*(N3z/16)*32/256, 256>>>(Wqkv);
    prep_wo_kernel<<<(DIMz/16)*(DIMz/16)*32/256, 256>>>(Wout);

    qkv_mma_kernel<<<dim3(N3z / 128, Mz / 128), 256, GEMM_SMEM_BYTES>>>();

    prep_vf_kernel<<<512, 256>>>();

    attn_mma_kernel<<<dim3(Tz / 128, Hz, Bz), 256, ATTN_SMEM_BYTES>>>();

    prep_att_kernel<<<(Mz/16)*(DIMz/16)*32/256, 256>>>();
    proj_mma_kernel<<<dim3(DIMz / 128, Mz / 128), 256, GEMM_SMEM_BYTES>>>(bout, out);
}